// round 11
// baseline (speedup 1.0000x reference)
#include <cuda_runtime.h>
#include <cuda_bf16.h>
#include <cstdint>
#include <math.h>

#define NN 49920
#define EE 200000
#define BB 128
#define HH 4
#define D1 1024
#define D2 256
#define NB ((NN + 255) / 256)   // 195

typedef __nv_bfloat16 bf16;

// ---------------- scratch ----------------
__device__ float g_xlr1[(size_t)NN * 2048];   // [xl1 | xr1]
__device__ float g_xlr2[(size_t)NN * 512];    // [xl2 | xr2]
__device__ float g_ef1[(size_t)EE * D1];
__device__ float g_ef2[(size_t)EE * D2];
__device__ float g_h2 [(size_t)NN * D2];

__device__ bf16 g_xh [(size_t)NN * 128],  g_xlo[(size_t)NN * 128];
__device__ bf16 g_eah[(size_t)EE * 16],   g_eal[(size_t)EE * 16];
__device__ bf16 g_h1h[(size_t)NN * D1],   g_h1l[(size_t)NN * D1];
__device__ bf16 g_w1h[128 * 2048],  g_w1l[128 * 2048];    // [Wl1 | Wr1]
__device__ bf16 g_w2h[1024 * 512],  g_w2l[1024 * 512];    // [Wl2 | Wr2]
__device__ bf16 g_we1h[16 * 1024],  g_we1l[16 * 1024];
__device__ bf16 g_we2h[16 * 256],   g_we2l[16 * 256];

__device__ int g_src[EE];
__device__ int g_dst[EE];
__device__ int g_cnt[NN];
__device__ int g_cur[NN];
__device__ int g_offs[NN + 1];
__device__ int g_perm[EE];
__device__ int g_part[256];

// ---------------- streams/events (created once pre-main) ----------------
static cudaStream_t g_s1, g_s2;
static cudaEvent_t g_evF, g_evJ1, g_evJ2, g_evJ3;
static struct StreamInit {
    StreamInit() {
        cudaStreamCreateWithFlags(&g_s1, cudaStreamNonBlocking);
        cudaStreamCreateWithFlags(&g_s2, cudaStreamNonBlocking);
        cudaEventCreateWithFlags(&g_evF,  cudaEventDisableTiming);
        cudaEventCreateWithFlags(&g_evJ1, cudaEventDisableTiming);
        cudaEventCreateWithFlags(&g_evJ2, cudaEventDisableTiming);
        cudaEventCreateWithFlags(&g_evJ3, cudaEventDisableTiming);
    }
} g_streamInit;

// ---------------- CSR build ----------------
__global__ void k_zero()
{
    int i = blockIdx.x * blockDim.x + threadIdx.x;
    if (i < NN) { g_cnt[i] = 0; g_cur[i] = 0; }
}

__global__ void k_convert(const void* __restrict__ ei)
{
    int e = blockIdx.x * blockDim.x + threadIdx.x;
    if (e >= EE) return;
    const int* w = (const int*)ei;
    bool is64 = true;
#pragma unroll
    for (int i = 1; i < 16; i += 2) is64 = is64 && (w[i] == 0);
    if (is64) {
        const long long* l = (const long long*)ei;
        g_src[e] = (int)l[e];
        g_dst[e] = (int)l[(size_t)EE + e];
    } else {
        g_src[e] = w[e];
        g_dst[e] = w[EE + e];
    }
}

__global__ void k_count()
{
    int e = blockIdx.x * blockDim.x + threadIdx.x;
    if (e < EE) atomicAdd(&g_cnt[g_dst[e]], 1);
}

__global__ void k_scanA()
{
    __shared__ int sw[8];
    int t = threadIdx.x;
    int i = blockIdx.x * 256 + t;
    int v = (i < NN) ? g_cnt[i] : 0;
#pragma unroll
    for (int off = 16; off; off >>= 1) v += __shfl_xor_sync(0xffffffffu, v, off);
    if ((t & 31) == 0) sw[t >> 5] = v;
    __syncthreads();
    if (t == 0) {
        int s = 0;
#pragma unroll
        for (int j = 0; j < 8; j++) s += sw[j];
        g_part[blockIdx.x] = s;
    }
}

__global__ void k_scanB()
{
    __shared__ int s[256];
    int t = threadIdx.x;
    int v = (t < NB) ? g_part[t] : 0;
    s[t] = v;
    __syncthreads();
    for (int off = 1; off < 256; off <<= 1) {
        int add = (t >= off) ? s[t - off] : 0;
        __syncthreads();
        s[t] += add;
        __syncthreads();
    }
    g_part[t] = s[t] - v;
}

__global__ void k_scanC()
{
    __shared__ int s[256];
    int t = threadIdx.x;
    int i = blockIdx.x * 256 + t;
    int v = (i < NN) ? g_cnt[i] : 0;
    s[t] = v;
    __syncthreads();
    for (int off = 1; off < 256; off <<= 1) {
        int add = (t >= off) ? s[t - off] : 0;
        __syncthreads();
        s[t] += add;
        __syncthreads();
    }
    if (i < NN) g_offs[i] = g_part[blockIdx.x] + s[t] - v;
    if (i == NN - 1) g_offs[NN] = EE;
}

__global__ void k_scatter()
{
    int e = blockIdx.x * blockDim.x + threadIdx.x;
    if (e >= EE) return;
    int d = g_dst[e];
    int p = g_offs[d] + atomicAdd(&g_cur[d], 1);
    g_perm[p] = e;
}

// ---------------- bf16 hi/lo split ----------------
__global__ void k_split(const float* __restrict__ src, bf16* __restrict__ hi,
                        bf16* __restrict__ lo, int n)
{
    int i = blockIdx.x * blockDim.x + threadIdx.x;
    if (i >= n) return;
    float v = src[i];
    bf16 h = __float2bfloat16_rn(v);
    hi[i] = h;
    lo[i] = __float2bfloat16_rn(v - __bfloat162float(h));
}

__global__ void k_split2(const float* __restrict__ src, bf16* __restrict__ hi,
                         bf16* __restrict__ lo, int K, int Nsrc, int Ndst, int coff)
{
    int i = blockIdx.x * blockDim.x + threadIdx.x;
    if (i >= K * Nsrc) return;
    int r = i / Nsrc, c = i % Nsrc;
    float v = src[i];
    bf16 h = __float2bfloat16_rn(v);
    size_t o = (size_t)r * Ndst + coff + c;
    hi[o] = h;
    lo[o] = __float2bfloat16_rn(v - __bfloat162float(h));
}

// ---------------- bf16x3 tensor-core GEMM, block tile 128x256 ----------------
// 256 threads, 8 warps in 2x4 grid (wm in {0,1} x 64 rows, wn in {0..3} x 64 cols).
// Warp tile 64x64: B fragments reused across 4 M-subtiles -> low smem/mma.
#define AST 40    // A smem row stride (bf16): 32 cols + pad
#define BST 264   // B smem row stride (bf16): 256 cols + pad (33 x 16B, odd)
#define A_HALF (128 * AST)
#define B_HALF (32 * BST)
#define STAGE_ELEMS (2 * A_HALF + 2 * B_HALF)
#define SMEM_BYTES (2 * STAGE_ELEMS * 2)

__device__ __forceinline__ void cpa16(unsigned dst, const void* src, int sz)
{
    asm volatile("cp.async.cg.shared.global [%0], [%1], 16, %2;\n"
                 :: "r"(dst), "l"(src), "r"(sz));
}
__device__ __forceinline__ void ldsm_x4(unsigned* r, unsigned a)
{
    asm volatile("ldmatrix.sync.aligned.m8n8.x4.shared.b16 {%0,%1,%2,%3}, [%4];\n"
                 : "=r"(r[0]), "=r"(r[1]), "=r"(r[2]), "=r"(r[3]) : "r"(a));
}
__device__ __forceinline__ void ldsm_x2t(unsigned* r, unsigned a)
{
    asm volatile("ldmatrix.sync.aligned.m8n8.x2.trans.shared.b16 {%0,%1}, [%2];\n"
                 : "=r"(r[0]), "=r"(r[1]) : "r"(a));
}
__device__ __forceinline__ void mma16816(float* d, const unsigned* a, const unsigned* b)
{
    asm volatile(
        "mma.sync.aligned.m16n8k16.row.col.f32.bf16.bf16.f32 "
        "{%0,%1,%2,%3}, {%4,%5,%6,%7}, {%8,%9}, {%0,%1,%2,%3};\n"
        : "+f"(d[0]), "+f"(d[1]), "+f"(d[2]), "+f"(d[3])
        : "r"(a[0]), "r"(a[1]), "r"(a[2]), "r"(a[3]), "r"(b[0]), "r"(b[1]));
}

// bias = biasA[0:nsplit] | biasB[nsplit:]; null biasA -> no bias
__global__ __launch_bounds__(256, 1) void k_gemm_bf3(const bf16* __restrict__ Ah,
                                                     const bf16* __restrict__ Al,
                                                     const bf16* __restrict__ Bh,
                                                     const bf16* __restrict__ Bl,
                                                     const float* __restrict__ biasA,
                                                     const float* __restrict__ biasB,
                                                     int nsplit,
                                                     float* __restrict__ C,
                                                     int M, int K, int Ncol)
{
    extern __shared__ bf16 smem[];
    const int tid = threadIdx.x;
    const int lane = tid & 31, w = tid >> 5;
    const int wm = w & 1, wn = w >> 1;        // 2 x 4 warp grid, warp tile 64x64
    const int m0 = blockIdx.y * 128, n0 = blockIdx.x * 256;
    const int r4 = lane >> 2, c4 = lane & 3;

    float acc[4][8][4];
#pragma unroll
    for (int i = 0; i < 4; i++)
#pragma unroll
        for (int j = 0; j < 8; j++)
#pragma unroll
            for (int r = 0; r < 4; r++) acc[i][j][r] = 0.f;

    const int T = (K + 31) / 32;

    auto load_stage = [&](int it) {
        const int k0 = it * 32;
        bf16* S = smem + (it & 1) * STAGE_ELEMS;
        // A: 2 parts x 128 rows x 4 chunks(16B) = 1024 chunks
#pragma unroll
        for (int q = 0; q < 4; q++) {
            int f = tid + q * 256;
            int hl = f >> 9;
            int r = (f >> 2) & 127;
            int ck = (f & 3) * 8;
            const bf16* src = hl ? Al : Ah;
            bool ok = (m0 + r < M) && (k0 + ck < K);
            const bf16* sp = ok ? (src + (size_t)(m0 + r) * K + k0 + ck) : src;
            bf16* dp = S + hl * A_HALF + r * AST + ck;
            cpa16((unsigned)__cvta_generic_to_shared(dp), sp, ok ? 16 : 0);
        }
        // B: 2 parts x 32 rows x 32 chunks(16B) = 2048 chunks
#pragma unroll
        for (int q = 0; q < 8; q++) {
            int f = tid + q * 256;
            int hl = f >> 10;
            int r = (f >> 5) & 31;
            int cn = (f & 31) * 8;
            const bf16* src = hl ? Bl : Bh;
            bool ok = (k0 + r < K);
            const bf16* sp = ok ? (src + (size_t)(k0 + r) * Ncol + n0 + cn) : src;
            bf16* dp = S + 2 * A_HALF + hl * B_HALF + r * BST + cn;
            cpa16((unsigned)__cvta_generic_to_shared(dp), sp, ok ? 16 : 0);
        }
        asm volatile("cp.async.commit_group;\n");
    };

    load_stage(0);

    for (int it = 0; it < T; it++) {
        if (it + 1 < T) {
            load_stage(it + 1);
            asm volatile("cp.async.wait_group 1;\n");
        } else {
            asm volatile("cp.async.wait_group 0;\n");
        }
        __syncthreads();

        const bf16* S = smem + (it & 1) * STAGE_ELEMS;
        const bf16* sAh = S;
        const bf16* sAl = S + A_HALF;
        const bf16* sBh = S + 2 * A_HALF;
        const bf16* sBl = S + 2 * A_HALF + B_HALF;

#pragma unroll
        for (int ks = 0; ks < 32; ks += 16) {
            unsigned aFh[4][4], aFl[4][4];
#pragma unroll
            for (int mt = 0; mt < 4; mt++) {
                int row = wm * 64 + mt * 16 + (lane & 7) + ((lane >> 3) & 1) * 8;
                int col = ks + (lane >> 4) * 8;
                ldsm_x4(aFh[mt], (unsigned)__cvta_generic_to_shared(sAh + row * AST + col));
                ldsm_x4(aFl[mt], (unsigned)__cvta_generic_to_shared(sAl + row * AST + col));
            }
#pragma unroll
            for (int nt = 0; nt < 8; nt++) {
                int brow = ks + (lane & 15);
                int bcol = wn * 64 + nt * 8;
                unsigned bFh[2], bFl[2];
                ldsm_x2t(bFh, (unsigned)__cvta_generic_to_shared(sBh + brow * BST + bcol));
                ldsm_x2t(bFl, (unsigned)__cvta_generic_to_shared(sBl + brow * BST + bcol));
#pragma unroll
                for (int mt = 0; mt < 4; mt++) {
                    mma16816(acc[mt][nt], aFh[mt], bFh);
                    mma16816(acc[mt][nt], aFl[mt], bFh);
                    mma16816(acc[mt][nt], aFh[mt], bFl);
                }
            }
        }
        __syncthreads();
    }

    auto bget = [&](int c) -> float {
        if (!biasA) return 0.f;
        return (c < nsplit) ? __ldg(biasA + c) : __ldg(biasB + c - nsplit);
    };

#pragma unroll
    for (int mt = 0; mt < 4; mt++) {
#pragma unroll
        for (int nt = 0; nt < 8; nt++) {
            int r = m0 + wm * 64 + mt * 16 + r4;
            int c = n0 + wn * 64 + nt * 8 + c4 * 2;
            float b0 = bget(c), b1 = bget(c + 1);
            if (r < M)
                *(float2*)(C + (size_t)r * Ncol + c) =
                    make_float2(acc[mt][nt][0] + b0, acc[mt][nt][1] + b1);
            if (r + 8 < M)
                *(float2*)(C + (size_t)(r + 8) * Ncol + c) =
                    make_float2(acc[mt][nt][2] + b0, acc[mt][nt][3] + b1);
        }
    }
}

// ---------------- fused GATv2 layer 1 ----------------
// thread t owns channels [4t, 4t+4); head = t>>6; 2 edges per iteration
__global__ __launch_bounds__(256) void k_gat1(const float* __restrict__ att,
                                              const float* __restrict__ bias)
{
    const int node = blockIdx.x;
    const int t = threadIdx.x;
    const int c0 = t * 4;
    const int h = t >> 6;
    const int w = t >> 5, lane = t & 31;
    __shared__ float4 xr_s[256], att_s[256];
    __shared__ float wp[8][2];
    __shared__ float sm_m[4], sm_d[4], sm_S[4], sm_W0[4], sm_W1[4];

    xr_s[t]  = *(const float4*)(g_xlr1 + (size_t)node * 2048 + 1024 + c0);
    att_s[t] = *(const float4*)(att + c0);
    if (t < 4) { sm_m[t] = -1e30f; sm_d[t] = 0.f; }
    __syncthreads();

    float4 acc = make_float4(0.f, 0.f, 0.f, 0.f);
    const int beg = g_offs[node], end = g_offs[node + 1];
    const float4 xr = xr_s[t], a4 = att_s[t];

    for (int k = beg; k < end; k += 2) {
        const bool two = (k + 1 < end);
        const int e0 = g_perm[k];
        const int e1 = two ? g_perm[k + 1] : e0;
        const int s0 = g_src[e0];
        const int s1 = two ? g_src[e1] : s0;

        float4 xl0 = *(const float4*)(g_xlr1 + (size_t)s0 * 2048 + c0);
        float4 ef0 = *(const float4*)(g_ef1 + (size_t)e0 * 1024 + c0);
        float4 xl1 = *(const float4*)(g_xlr1 + (size_t)s1 * 2048 + c0);
        float4 ef1 = *(const float4*)(g_ef1 + (size_t)e1 * 1024 + c0);

        float p0, p1;
        {
            float v0 = xl0.x + xr.x + ef0.x, v1 = xl0.y + xr.y + ef0.y;
            float v2 = xl0.z + xr.z + ef0.z, v3 = xl0.w + xr.w + ef0.w;
            v0 = v0 > 0.f ? v0 : 0.2f * v0; v1 = v1 > 0.f ? v1 : 0.2f * v1;
            v2 = v2 > 0.f ? v2 : 0.2f * v2; v3 = v3 > 0.f ? v3 : 0.2f * v3;
            p0 = a4.x * v0 + a4.y * v1 + a4.z * v2 + a4.w * v3;
        }
        {
            float v0 = xl1.x + xr.x + ef1.x, v1 = xl1.y + xr.y + ef1.y;
            float v2 = xl1.z + xr.z + ef1.z, v3 = xl1.w + xr.w + ef1.w;
            v0 = v0 > 0.f ? v0 : 0.2f * v0; v1 = v1 > 0.f ? v1 : 0.2f * v1;
            v2 = v2 > 0.f ? v2 : 0.2f * v2; v3 = v3 > 0.f ? v3 : 0.2f * v3;
            p1 = a4.x * v0 + a4.y * v1 + a4.z * v2 + a4.w * v3;
        }
#pragma unroll
        for (int off = 16; off; off >>= 1) {
            p0 += __shfl_xor_sync(0xffffffffu, p0, off);
            p1 += __shfl_xor_sync(0xffffffffu, p1, off);
        }
        if (lane == 0) { wp[w][0] = p0; wp[w][1] = p1; }
        __syncthreads();
        if (t < 4) {
            float l0 = wp[2 * t][0] + wp[2 * t + 1][0];
            float m = sm_m[t], d = sm_d[t];
            float mn = fmaxf(m, l0);
            float sc0 = __expf(m - mn), w0 = __expf(l0 - mn);
            d = d * sc0 + w0; m = mn;
            float sc1 = 1.f, w1 = 0.f;
            if (two) {
                float l1 = wp[2 * t][1] + wp[2 * t + 1][1];
                mn = fmaxf(m, l1);
                sc1 = __expf(m - mn); w1 = __expf(l1 - mn);
                d = d * sc1 + w1; m = mn;
            }
            sm_m[t] = m; sm_d[t] = d;
            sm_S[t] = sc0 * sc1; sm_W0[t] = w0 * sc1; sm_W1[t] = w1;
        }
        __syncthreads();
        float S = sm_S[h], W0 = sm_W0[h], W1 = sm_W1[h];
        acc.x = acc.x * S + W0 * xl0.x + W1 * xl1.x;
        acc.y = acc.y * S + W0 * xl0.y + W1 * xl1.y;
        acc.z = acc.z * S + W0 * xl0.z + W1 * xl1.z;
        acc.w = acc.w * S + W0 * xl0.w + W1 * xl1.w;
    }

    float inv = 1.f / (sm_d[h] + 1e-16f);
    float4 bv = *(const float4*)(bias + c0);
    float o0 = fmaxf(acc.x * inv + bv.x, 0.f);
    float o1 = fmaxf(acc.y * inv + bv.y, 0.f);
    float o2 = fmaxf(acc.z * inv + bv.z, 0.f);
    float o3 = fmaxf(acc.w * inv + bv.w, 0.f);
    bf16 h0 = __float2bfloat16_rn(o0), h1v = __float2bfloat16_rn(o1);
    bf16 h2 = __float2bfloat16_rn(o2), h3 = __float2bfloat16_rn(o3);
    bf16* ph = g_h1h + (size_t)node * D1 + c0;
    bf16* pl = g_h1l + (size_t)node * D1 + c0;
    ph[0] = h0; ph[1] = h1v; ph[2] = h2; ph[3] = h3;
    pl[0] = __float2bfloat16_rn(o0 - __bfloat162float(h0));
    pl[1] = __float2bfloat16_rn(o1 - __bfloat162float(h1v));
    pl[2] = __float2bfloat16_rn(o2 - __bfloat162float(h2));
    pl[3] = __float2bfloat16_rn(o3 - __bfloat162float(h3));
}

// ---------------- fused GATv2 layer 2 ----------------
__global__ __launch_bounds__(256) void k_gat2(const float* __restrict__ att,
                                              const float* __restrict__ bias)
{
    const int node = blockIdx.x;
    const int t = threadIdx.x;
    const int h = t >> 6;
    const int w = t >> 5, lane = t & 31;
    __shared__ float xr_s[D2], att_s[D2];
    __shared__ float wp[8][2];
    __shared__ float sm_m[4], sm_d[4], sm_S[4], sm_W0[4], sm_W1[4];

    xr_s[t]  = g_xlr2[(size_t)node * 512 + 256 + t];
    att_s[t] = att[t];
    if (t < 4) { sm_m[t] = -1e30f; sm_d[t] = 0.f; }
    __syncthreads();

    float acc = 0.f;
    const int beg = g_offs[node], end = g_offs[node + 1];
    const float xr = xr_s[t], av = att_s[t];

    for (int k = beg; k < end; k += 2) {
        const bool two = (k + 1 < end);
        const int e0 = g_perm[k];
        const int e1 = two ? g_perm[k + 1] : e0;
        const int s0 = g_src[e0];
        const int s1 = two ? g_src[e1] : s0;

        float xl0 = g_xlr2[(size_t)s0 * 512 + t];
        float ef0 = g_ef2[(size_t)e0 * 256 + t];
        float xl1 = g_xlr2[(size_t)s1 * 512 + t];
        float ef1 = g_ef2[(size_t)e1 * 256 + t];

        float v0 = xl0 + xr + ef0;
        float v1 = xl1 + xr + ef1;
        v0 = v0 > 0.f ? v0 : 0.2f * v0;
        v1 = v1 > 0.f ? v1 : 0.2f * v1;
        float p0 = av * v0, p1 = av * v1;
#pragma unroll
        for (int off = 16; off; off >>= 1) {
            p0 += __shfl_xor_sync(0xffffffffu, p0, off);
            p1 += __shfl_xor_sync(0xffffffffu, p1, off);
        }
        if (lane == 0) { wp[w][0] = p0; wp[w][1] = p1; }
        __syncthreads();
        if (t < 4) {
            float l0 = wp[2 * t][0] + wp[2 * t + 1][0];
            float m = sm_m[t], d = sm_d[t];
            float mn = fmaxf(m, l0);
            float sc0 = __expf(m - mn), w0 = __expf(l0 - mn);
            d = d * sc0 + w0; m = mn;
            float sc1 = 1.f, w1 = 0.f;
            if (two) {
                float l1 = wp[2 * t][1] + wp[2 * t + 1][1];
                mn = fmaxf(m, l1);
                sc1 = __expf(m - mn); w1 = __expf(l1 - mn);
                d = d * sc1 + w1; m = mn;
            }
            sm_m[t] = m; sm_d[t] = d;
            sm_S[t] = sc0 * sc1; sm_W0[t] = w0 * sc1; sm_W1[t] = w1;
        }
        __syncthreads();
        acc = acc * sm_S[h] + sm_W0[h] * xl0 + sm_W1[h] * xl1;
    }

    float o = acc / (sm_d[h] + 1e-16f);
    g_h2[(size_t)node * D2 + t] = fmaxf(o + bias[t], 0.f);
}

// ---------------- MLP head ----------------
__global__ void k_mlp(const void* __restrict__ n_nodes,
                      const float* __restrict__ fc1w, const float* __restrict__ fc1b,
                      const float* __restrict__ fc2w, const float* __restrict__ fc2b,
                      float* __restrict__ out)
{
    const int b = blockIdx.x;
    const int t = threadIdx.x;  // 64
    __shared__ float master[D2];
    __shared__ int s_last;
    __shared__ float ws[2];

    if (t == 0) {
        const int* w = (const int*)n_nodes;
        bool is64 = (w[1] == 0);
        long long cum = 0;
        if (is64) {
            const long long* l = (const long long*)n_nodes;
            for (int i = 0; i <= b; i++) cum += l[i];
        } else {
            for (int i = 0; i <= b; i++) cum += w[i];
        }
        s_last = (int)cum - 1;
    }
    __syncthreads();
    const int node = s_last;
    for (int i = t; i < D2; i += 64) master[i] = g_h2[(size_t)node * D2 + i];
    __syncthreads();

    float z = fc1b[t];
    for (int c = 0; c < D2; c++) z += master[c] * fc1w[c * 64 + t];
    z = fmaxf(z, 0.f);
    float v = z * fc2w[t];
#pragma unroll
    for (int off = 16; off; off >>= 1) v += __shfl_xor_sync(0xffffffffu, v, off);
    if ((t & 31) == 0) ws[t >> 5] = v;
    __syncthreads();
    if (t == 0) out[b] = ws[0] + ws[1] + fc2b[0];
}

// ---------------- launch ----------------
extern "C" void kernel_launch(void* const* d_in, const int* in_sizes, int n_in,
                              void* d_out, int out_size)
{
    const float* x    = (const float*)d_in[0];
    const void*  ei   = d_in[1];
    const float* ea   = (const float*)d_in[2];
    const void*  nnod = d_in[3];
    const float* Wl1  = (const float*)d_in[4];
    const float* bl1  = (const float*)d_in[5];
    const float* Wr1  = (const float*)d_in[6];
    const float* br1  = (const float*)d_in[7];
    const float* We1  = (const float*)d_in[8];
    const float* att1 = (const float*)d_in[9];
    const float* b1   = (const float*)d_in[10];
    const float* Wl2  = (const float*)d_in[11];
    const float* bl2  = (const float*)d_in[12];
    const float* Wr2  = (const float*)d_in[13];
    const float* br2  = (const float*)d_in[14];
    const float* We2  = (const float*)d_in[15];
    const float* att2 = (const float*)d_in[16];
    const float* b2   = (const float*)d_in[17];
    const float* fc1w = (const float*)d_in[18];
    const float* fc1b = (const float*)d_in[19];
    const float* fc2w = (const float*)d_in[20];
    const float* fc2b = (const float*)d_in[21];
    float* out = (float*)d_out;

    float *xlr1, *xlr2, *ef1, *ef2;
    bf16 *xh, *xlo, *eah, *eal, *h1h, *h1l, *w1h, *w1l, *w2h, *w2l;
    bf16 *we1h, *we1l, *we2h, *we2l;
    cudaGetSymbolAddress((void**)&xlr1, g_xlr1);
    cudaGetSymbolAddress((void**)&xlr2, g_xlr2);
    cudaGetSymbolAddress((void**)&ef1, g_ef1);
    cudaGetSymbolAddress((void**)&ef2, g_ef2);
    cudaGetSymbolAddress((void**)&xh,  g_xh);
    cudaGetSymbolAddress((void**)&xlo, g_xlo);
    cudaGetSymbolAddress((void**)&eah, g_eah);
    cudaGetSymbolAddress((void**)&eal, g_eal);
    cudaGetSymbolAddress((void**)&h1h, g_h1h);
    cudaGetSymbolAddress((void**)&h1l, g_h1l);
    cudaGetSymbolAddress((void**)&w1h, g_w1h); cudaGetSymbolAddress((void**)&w1l, g_w1l);
    cudaGetSymbolAddress((void**)&w2h, g_w2h); cudaGetSymbolAddress((void**)&w2l, g_w2l);
    cudaGetSymbolAddress((void**)&we1h, g_we1h); cudaGetSymbolAddress((void**)&we1l, g_we1l);
    cudaGetSymbolAddress((void**)&we2h, g_we2h); cudaGetSymbolAddress((void**)&we2l, g_we2l);

    cudaFuncSetAttribute(k_gemm_bf3,
                         cudaFuncAttributeMaxDynamicSharedMemorySize, SMEM_BYTES);

    const int TB = 256;

    // fork point
    cudaEventRecord(g_evF, 0);

    // ---- main stream: splits for layer-1 GEMM, then layer-1 GEMM ----
    k_split<<<(NN * 128 + 255) / 256, 256>>>(x, xh, xlo, NN * 128);
    k_split2<<<(128 * 1024 + 255) / 256, 256>>>(Wl1, w1h, w1l, 128, 1024, 2048, 0);
    k_split2<<<(128 * 1024 + 255) / 256, 256>>>(Wr1, w1h, w1l, 128, 1024, 2048, 1024);
    {
        dim3 g1(2048 / 256, NN / 128);
        k_gemm_bf3<<<g1, 256, SMEM_BYTES>>>(xh, xlo, w1h, w1l, bl1, br1, 1024,
                                            xlr1, NN, 128, 2048);
    }

    // ---- s1: edge-feature splits + ef GEMMs ----
    cudaStreamWaitEvent(g_s1, g_evF, 0);
    k_split<<<(EE * 16 + 255) / 256, 256, 0, g_s1>>>(ea, eah, eal, EE * 16);
    k_split<<<(16 * 1024 + 255) / 256, 256, 0, g_s1>>>(We1, we1h, we1l, 16 * 1024);
    {
        dim3 ge(1024 / 256, (EE + 127) / 128);
        k_gemm_bf3<<<ge, 256, SMEM_BYTES, g_s1>>>(eah, eal, we1h, we1l,
                                                  nullptr, nullptr, 0,
                                                  ef1, EE, 16, 1024);
    }
    cudaEventRecord(g_evJ2, g_s1);                 // ef1 ready
    k_split<<<(16 * 256 + 255) / 256, 256, 0, g_s1>>>(We2, we2h, we2l, 16 * 256);
    {
        dim3 ge(256 / 256, (EE + 127) / 128);
        k_gemm_bf3<<<ge, 256, SMEM_BYTES, g_s1>>>(eah, eal, we2h, we2l,
                                                  nullptr, nullptr, 0,
                                                  ef2, EE, 16, 256);
    }
    cudaEventRecord(g_evJ3, g_s1);                 // ef2 ready

    // ---- s2: CSR build + layer-2 weight splits ----
    cudaStreamWaitEvent(g_s2, g_evF, 0);
    k_zero<<<(NN + TB - 1) / TB, TB, 0, g_s2>>>();
    k_convert<<<(EE + TB - 1) / TB, TB, 0, g_s2>>>(ei);
    k_count<<<(EE + TB - 1) / TB, TB, 0, g_s2>>>();
    k_scanA<<<NB, 256, 0, g_s2>>>();
    k_scanB<<<1, 256, 0, g_s2>>>();
    k_scanC<<<NB, 256, 0, g_s2>>>();
    k_scatter<<<(EE + TB - 1) / TB, TB, 0, g_s2>>>();
    k_split2<<<(1024 * 256 + 255) / 256, 256, 0, g_s2>>>(Wl2, w2h, w2l, 1024, 256, 512, 0);
    k_split2<<<(1024 * 256 + 255) / 256, 256, 0, g_s2>>>(Wr2, w2h, w2l, 1024, 256, 512, 256);
    cudaEventRecord(g_evJ1, g_s2);                 // CSR + W2 ready

    // ---- main: join and continue ----
    cudaStreamWaitEvent(0, g_evJ1, 0);
    cudaStreamWaitEvent(0, g_evJ2, 0);
    k_gat1<<<NN, 256>>>(att1, b1);
    {
        dim3 g2(512 / 256, NN / 128);
        k_gemm_bf3<<<g2, 256, SMEM_BYTES>>>(h1h, h1l, w2h, w2l, bl2, br2, 256,
                                            xlr2, NN, 1024, 512);
    }
    cudaStreamWaitEvent(0, g_evJ3, 0);
    k_gat2<<<NN, 256>>>(att2, b2);

    k_mlp<<<BB, 64>>>(nnod, fc1w, fc1b, fc2w, fc2b, out);
}

// round 13
// speedup vs baseline: 1.0482x; 1.0482x over previous
#include <cuda_runtime.h>
#include <cuda_bf16.h>
#include <cstdint>
#include <math.h>

#define NN 49920
#define EE 200000
#define BB 128
#define HH 4
#define D1 1024
#define D2 256
#define NB ((NN + 255) / 256)   // 195

typedef __nv_bfloat16 bf16;

// ---------------- scratch ----------------
__device__ float g_xlr1[(size_t)NN * 2048];   // [xl1 | xr1]
__device__ float g_xlr2[(size_t)NN * 512];    // [xl2 | xr2]
__device__ float g_ef1[(size_t)EE * D1];
__device__ float g_ef2[(size_t)EE * D2];
__device__ float g_h2 [(size_t)NN * D2];

__device__ bf16 g_xh [(size_t)NN * 128],  g_xlo[(size_t)NN * 128];
__device__ bf16 g_eah[(size_t)EE * 16],   g_eal[(size_t)EE * 16];
__device__ bf16 g_h1h[(size_t)NN * D1],   g_h1l[(size_t)NN * D1];
__device__ bf16 g_w1h[128 * 2048],  g_w1l[128 * 2048];    // [Wl1 | Wr1]
__device__ bf16 g_w2h[1024 * 512],  g_w2l[1024 * 512];    // [Wl2 | Wr2]
__device__ bf16 g_we1h[16 * 1024],  g_we1l[16 * 1024];
__device__ bf16 g_we2h[16 * 256],   g_we2l[16 * 256];

__device__ int g_src[EE];
__device__ int g_dst[EE];
__device__ int g_cnt[NN];
__device__ int g_cur[NN];
__device__ int g_offs[NN + 1];
__device__ int g_perm[EE];
__device__ int g_part[256];

// ---------------- streams/events (created once pre-main) ----------------
static cudaStream_t g_s1, g_s2;
static cudaEvent_t g_evF, g_evJ1, g_evJ2, g_evJ3;
static struct StreamInit {
    StreamInit() {
        cudaStreamCreateWithFlags(&g_s1, cudaStreamNonBlocking);
        cudaStreamCreateWithFlags(&g_s2, cudaStreamNonBlocking);
        cudaEventCreateWithFlags(&g_evF,  cudaEventDisableTiming);
        cudaEventCreateWithFlags(&g_evJ1, cudaEventDisableTiming);
        cudaEventCreateWithFlags(&g_evJ2, cudaEventDisableTiming);
        cudaEventCreateWithFlags(&g_evJ3, cudaEventDisableTiming);
    }
} g_streamInit;

// ---------------- CSR build ----------------
__global__ void k_zero()
{
    int i = blockIdx.x * blockDim.x + threadIdx.x;
    if (i < NN) { g_cnt[i] = 0; g_cur[i] = 0; }
}

__global__ void k_convert(const void* __restrict__ ei)
{
    int e = blockIdx.x * blockDim.x + threadIdx.x;
    if (e >= EE) return;
    const int* w = (const int*)ei;
    bool is64 = true;
#pragma unroll
    for (int i = 1; i < 16; i += 2) is64 = is64 && (w[i] == 0);
    if (is64) {
        const long long* l = (const long long*)ei;
        g_src[e] = (int)l[e];
        g_dst[e] = (int)l[(size_t)EE + e];
    } else {
        g_src[e] = w[e];
        g_dst[e] = w[EE + e];
    }
}

__global__ void k_count()
{
    int e = blockIdx.x * blockDim.x + threadIdx.x;
    if (e < EE) atomicAdd(&g_cnt[g_dst[e]], 1);
}

__global__ void k_scanA()
{
    __shared__ int sw[8];
    int t = threadIdx.x;
    int i = blockIdx.x * 256 + t;
    int v = (i < NN) ? g_cnt[i] : 0;
#pragma unroll
    for (int off = 16; off; off >>= 1) v += __shfl_xor_sync(0xffffffffu, v, off);
    if ((t & 31) == 0) sw[t >> 5] = v;
    __syncthreads();
    if (t == 0) {
        int s = 0;
#pragma unroll
        for (int j = 0; j < 8; j++) s += sw[j];
        g_part[blockIdx.x] = s;
    }
}

__global__ void k_scanB()
{
    __shared__ int s[256];
    int t = threadIdx.x;
    int v = (t < NB) ? g_part[t] : 0;
    s[t] = v;
    __syncthreads();
    for (int off = 1; off < 256; off <<= 1) {
        int add = (t >= off) ? s[t - off] : 0;
        __syncthreads();
        s[t] += add;
        __syncthreads();
    }
    g_part[t] = s[t] - v;
}

__global__ void k_scanC()
{
    __shared__ int s[256];
    int t = threadIdx.x;
    int i = blockIdx.x * 256 + t;
    int v = (i < NN) ? g_cnt[i] : 0;
    s[t] = v;
    __syncthreads();
    for (int off = 1; off < 256; off <<= 1) {
        int add = (t >= off) ? s[t - off] : 0;
        __syncthreads();
        s[t] += add;
        __syncthreads();
    }
    if (i < NN) g_offs[i] = g_part[blockIdx.x] + s[t] - v;
    if (i == NN - 1) g_offs[NN] = EE;
}

__global__ void k_scatter()
{
    int e = blockIdx.x * blockDim.x + threadIdx.x;
    if (e >= EE) return;
    int d = g_dst[e];
    int p = g_offs[d] + atomicAdd(&g_cur[d], 1);
    g_perm[p] = e;
}

// ---------------- bf16 hi/lo split ----------------
__global__ void k_split(const float* __restrict__ src, bf16* __restrict__ hi,
                        bf16* __restrict__ lo, int n)
{
    int i = blockIdx.x * blockDim.x + threadIdx.x;
    if (i >= n) return;
    float v = src[i];
    bf16 h = __float2bfloat16_rn(v);
    hi[i] = h;
    lo[i] = __float2bfloat16_rn(v - __bfloat162float(h));
}

__global__ void k_split2(const float* __restrict__ src, bf16* __restrict__ hi,
                         bf16* __restrict__ lo, int K, int Nsrc, int Ndst, int coff)
{
    int i = blockIdx.x * blockDim.x + threadIdx.x;
    if (i >= K * Nsrc) return;
    int r = i / Nsrc, c = i % Nsrc;
    float v = src[i];
    bf16 h = __float2bfloat16_rn(v);
    size_t o = (size_t)r * Ndst + coff + c;
    hi[o] = h;
    lo[o] = __float2bfloat16_rn(v - __bfloat162float(h));
}

// ---------------- bf16x3 tensor-core GEMM (round-7 proven config) ----------------
#define AST 40
#define BST 136
#define A_HALF (128 * AST)
#define B_HALF (32 * BST)
#define STAGE_ELEMS (2 * A_HALF + 2 * B_HALF)
#define SMEM_BYTES (2 * STAGE_ELEMS * 2)

__device__ __forceinline__ void cpa16(unsigned dst, const void* src, int sz)
{
    asm volatile("cp.async.cg.shared.global [%0], [%1], 16, %2;\n"
                 :: "r"(dst), "l"(src), "r"(sz));
}
__device__ __forceinline__ void ldsm_x4(unsigned* r, unsigned a)
{
    asm volatile("ldmatrix.sync.aligned.m8n8.x4.shared.b16 {%0,%1,%2,%3}, [%4];\n"
                 : "=r"(r[0]), "=r"(r[1]), "=r"(r[2]), "=r"(r[3]) : "r"(a));
}
__device__ __forceinline__ void ldsm_x2t(unsigned* r, unsigned a)
{
    asm volatile("ldmatrix.sync.aligned.m8n8.x2.trans.shared.b16 {%0,%1}, [%2];\n"
                 : "=r"(r[0]), "=r"(r[1]) : "r"(a));
}
__device__ __forceinline__ void mma16816(float* d, const unsigned* a, const unsigned* b)
{
    asm volatile(
        "mma.sync.aligned.m16n8k16.row.col.f32.bf16.bf16.f32 "
        "{%0,%1,%2,%3}, {%4,%5,%6,%7}, {%8,%9}, {%0,%1,%2,%3};\n"
        : "+f"(d[0]), "+f"(d[1]), "+f"(d[2]), "+f"(d[3])
        : "r"(a[0]), "r"(a[1]), "r"(a[2]), "r"(a[3]), "r"(b[0]), "r"(b[1]));
}

// bias = biasA[0:nsplit] | biasB[nsplit:]; null biasA -> no bias
__global__ __launch_bounds__(256, 2) void k_gemm_bf3(const bf16* __restrict__ Ah,
                                                     const bf16* __restrict__ Al,
                                                     const bf16* __restrict__ Bh,
                                                     const bf16* __restrict__ Bl,
                                                     const float* __restrict__ biasA,
                                                     const float* __restrict__ biasB,
                                                     int nsplit,
                                                     float* __restrict__ C,
                                                     int M, int K, int Ncol)
{
    extern __shared__ bf16 smem[];
    const int tid = threadIdx.x;
    const int lane = tid & 31, w = tid >> 5;
    const int wm = w & 3, wn = w >> 2;        // 4 x 2 warp grid, tile 32x64
    const int m0 = blockIdx.y * 128, n0 = blockIdx.x * 128;

    float acc[2][8][4];
#pragma unroll
    for (int i = 0; i < 2; i++)
#pragma unroll
        for (int j = 0; j < 8; j++)
#pragma unroll
            for (int r = 0; r < 4; r++) acc[i][j][r] = 0.f;

    const int T = (K + 31) / 32;

    auto load_stage = [&](int it) {
        const int k0 = it * 32;
        bf16* S = smem + (it & 1) * STAGE_ELEMS;
#pragma unroll
        for (int q = 0; q < 4; q++) {               // A: 1024 chunks of 16B
            int f = tid + q * 256;
            int hl = f >> 9;
            int r = (f >> 2) & 127;
            int ck = (f & 3) * 8;
            const bf16* src = hl ? Al : Ah;
            bool ok = (m0 + r < M) && (k0 + ck < K);
            const bf16* sp = ok ? (src + (size_t)(m0 + r) * K + k0 + ck) : src;
            bf16* dp = S + hl * A_HALF + r * AST + ck;
            cpa16((unsigned)__cvta_generic_to_shared(dp), sp, ok ? 16 : 0);
        }
#pragma unroll
        for (int q = 0; q < 4; q++) {               // B: 1024 chunks
            int f = tid + q * 256;
            int hl = f >> 9;
            int r = (f >> 4) & 31;
            int cn = (f & 15) * 8;
            const bf16* src = hl ? Bl : Bh;
            bool ok = (k0 + r < K);
            const bf16* sp = ok ? (src + (size_t)(k0 + r) * Ncol + n0 + cn) : src;
            bf16* dp = S + 2 * A_HALF + hl * B_HALF + r * BST + cn;
            cpa16((unsigned)__cvta_generic_to_shared(dp), sp, ok ? 16 : 0);
        }
        asm volatile("cp.async.commit_group;\n");
    };

    load_stage(0);

    for (int it = 0; it < T; it++) {
        if (it + 1 < T) {
            load_stage(it + 1);
            asm volatile("cp.async.wait_group 1;\n");
        } else {
            asm volatile("cp.async.wait_group 0;\n");
        }
        __syncthreads();

        const bf16* S = smem + (it & 1) * STAGE_ELEMS;
        const bf16* sAh = S;
        const bf16* sAl = S + A_HALF;
        const bf16* sBh = S + 2 * A_HALF;
        const bf16* sBl = S + 2 * A_HALF + B_HALF;

#pragma unroll
        for (int ks = 0; ks < 32; ks += 16) {
            unsigned aFh[2][4], aFl[2][4];
#pragma unroll
            for (int mt = 0; mt < 2; mt++) {
                int row = wm * 32 + mt * 16 + (lane & 7) + ((lane >> 3) & 1) * 8;
                int col = ks + (lane >> 4) * 8;
                ldsm_x4(aFh[mt], (unsigned)__cvta_generic_to_shared(sAh + row * AST + col));
                ldsm_x4(aFl[mt], (unsigned)__cvta_generic_to_shared(sAl + row * AST + col));
            }
#pragma unroll
            for (int nt = 0; nt < 8; nt++) {
                int brow = ks + (lane & 15);
                int bcol = wn * 64 + nt * 8;
                unsigned bFh[2], bFl[2];
                ldsm_x2t(bFh, (unsigned)__cvta_generic_to_shared(sBh + brow * BST + bcol));
                ldsm_x2t(bFl, (unsigned)__cvta_generic_to_shared(sBl + brow * BST + bcol));
#pragma unroll
                for (int mt = 0; mt < 2; mt++) {
                    mma16816(acc[mt][nt], aFh[mt], bFh);
                    mma16816(acc[mt][nt], aFl[mt], bFh);
                    mma16816(acc[mt][nt], aFh[mt], bFl);
                }
            }
        }
        __syncthreads();
    }

    auto bget = [&](int c) -> float {
        if (!biasA) return 0.f;
        return (c < nsplit) ? __ldg(biasA + c) : __ldg(biasB + c - nsplit);
    };

#pragma unroll
    for (int mt = 0; mt < 2; mt++) {
#pragma unroll
        for (int nt = 0; nt < 8; nt++) {
            int r = m0 + wm * 32 + mt * 16 + (lane >> 2);
            int c = n0 + wn * 64 + nt * 8 + (lane & 3) * 2;
            float b0 = bget(c), b1 = bget(c + 1);
            if (r < M)
                *(float2*)(C + (size_t)r * Ncol + c) =
                    make_float2(acc[mt][nt][0] + b0, acc[mt][nt][1] + b1);
            if (r + 8 < M)
                *(float2*)(C + (size_t)(r + 8) * Ncol + c) =
                    make_float2(acc[mt][nt][2] + b0, acc[mt][nt][3] + b1);
        }
    }
}

// ---------------- fused GATv2 layer 1 (4 edges per iteration) ----------------
// thread t owns channels [4t, 4t+4); head = t>>6 spans warps 2h, 2h+1
__global__ __launch_bounds__(256) void k_gat1(const float* __restrict__ att,
                                              const float* __restrict__ bias)
{
    const int node = blockIdx.x;
    const int t = threadIdx.x;
    const int c0 = t * 4;
    const int h = t >> 6;
    const int w = t >> 5, lane = t & 31;
    __shared__ float4 xr_s[256], att_s[256];
    __shared__ float wp[8][4];
    __shared__ float sm_m[4], sm_d[4], sm_S[4], sm_W[4][4];

    xr_s[t]  = *(const float4*)(g_xlr1 + (size_t)node * 2048 + 1024 + c0);
    att_s[t] = *(const float4*)(att + c0);
    if (t < 4) { sm_m[t] = -1e30f; sm_d[t] = 0.f; }
    __syncthreads();

    float4 acc = make_float4(0.f, 0.f, 0.f, 0.f);
    const int beg = g_offs[node], end = g_offs[node + 1];
    const float4 xr = xr_s[t], a4 = att_s[t];

    for (int k = beg; k < end; k += 4) {
        const int nv = min(4, end - k);
        float4 xl[4], ef[4];
        float p[4];
#pragma unroll
        for (int i = 0; i < 4; i++) {
            int kk = (k + i < end) ? k + i : k;
            int e = g_perm[kk];
            int s = g_src[e];
            xl[i] = *(const float4*)(g_xlr1 + (size_t)s * 2048 + c0);
            ef[i] = *(const float4*)(g_ef1 + (size_t)e * 1024 + c0);
        }
#pragma unroll
        for (int i = 0; i < 4; i++) {
            float v0 = xl[i].x + xr.x + ef[i].x, v1 = xl[i].y + xr.y + ef[i].y;
            float v2 = xl[i].z + xr.z + ef[i].z, v3 = xl[i].w + xr.w + ef[i].w;
            v0 = v0 > 0.f ? v0 : 0.2f * v0; v1 = v1 > 0.f ? v1 : 0.2f * v1;
            v2 = v2 > 0.f ? v2 : 0.2f * v2; v3 = v3 > 0.f ? v3 : 0.2f * v3;
            p[i] = a4.x * v0 + a4.y * v1 + a4.z * v2 + a4.w * v3;
        }
#pragma unroll
        for (int i = 0; i < 4; i++)
#pragma unroll
            for (int off = 16; off; off >>= 1)
                p[i] += __shfl_xor_sync(0xffffffffu, p[i], off);
        if (lane == 0) {
#pragma unroll
            for (int i = 0; i < 4; i++) wp[w][i] = p[i];
        }
        __syncthreads();
        if (t < 4) {
            float m = sm_m[t], d = sm_d[t];
            float sc[4], wv[4];
#pragma unroll
            for (int i = 0; i < 4; i++) {
                if (i < nv) {
                    float l = wp[2 * t][i] + wp[2 * t + 1][i];   // head t = warps 2t, 2t+1
                    float mn = fmaxf(m, l);
                    sc[i] = __expf(m - mn);
                    wv[i] = __expf(l - mn);
                    d = d * sc[i] + wv[i];
                    m = mn;
                } else { sc[i] = 1.f; wv[i] = 0.f; }
            }
            sm_m[t] = m; sm_d[t] = d;
            float s3 = sc[3], s23 = sc[2] * s3, s123 = sc[1] * s23;
            sm_S[t] = sc[0] * s123;
            sm_W[t][0] = wv[0] * s123;
            sm_W[t][1] = wv[1] * s23;
            sm_W[t][2] = wv[2] * s3;
            sm_W[t][3] = wv[3];
        }
        __syncthreads();
        float S = sm_S[h];
        float W0 = sm_W[h][0], W1 = sm_W[h][1], W2 = sm_W[h][2], W3 = sm_W[h][3];
        acc.x = acc.x * S + W0 * xl[0].x + W1 * xl[1].x + W2 * xl[2].x + W3 * xl[3].x;
        acc.y = acc.y * S + W0 * xl[0].y + W1 * xl[1].y + W2 * xl[2].y + W3 * xl[3].y;
        acc.z = acc.z * S + W0 * xl[0].z + W1 * xl[1].z + W2 * xl[2].z + W3 * xl[3].z;
        acc.w = acc.w * S + W0 * xl[0].w + W1 * xl[1].w + W2 * xl[2].w + W3 * xl[3].w;
    }

    float inv = 1.f / (sm_d[h] + 1e-16f);
    float4 bv = *(const float4*)(bias + c0);
    float o0 = fmaxf(acc.x * inv + bv.x, 0.f);
    float o1 = fmaxf(acc.y * inv + bv.y, 0.f);
    float o2 = fmaxf(acc.z * inv + bv.z, 0.f);
    float o3 = fmaxf(acc.w * inv + bv.w, 0.f);
    bf16 h0 = __float2bfloat16_rn(o0), h1v = __float2bfloat16_rn(o1);
    bf16 h2 = __float2bfloat16_rn(o2), h3 = __float2bfloat16_rn(o3);
    bf16* ph = g_h1h + (size_t)node * D1 + c0;
    bf16* pl = g_h1l + (size_t)node * D1 + c0;
    ph[0] = h0; ph[1] = h1v; ph[2] = h2; ph[3] = h3;
    pl[0] = __float2bfloat16_rn(o0 - __bfloat162float(h0));
    pl[1] = __float2bfloat16_rn(o1 - __bfloat162float(h1v));
    pl[2] = __float2bfloat16_rn(o2 - __bfloat162float(h2));
    pl[3] = __float2bfloat16_rn(o3 - __bfloat162float(h3));
}

// ---------------- fused GATv2 layer 2 (4 edges per iteration) ----------------
// channel = t, head = t>>6 spans warps 2h, 2h+1
__global__ __launch_bounds__(256) void k_gat2(const float* __restrict__ att,
                                              const float* __restrict__ bias)
{
    const int node = blockIdx.x;
    const int t = threadIdx.x;
    const int h = t >> 6;
    const int w = t >> 5, lane = t & 31;
    __shared__ float xr_s[D2], att_s[D2];
    __shared__ float wp[8][4];
    __shared__ float sm_m[4], sm_d[4], sm_S[4], sm_W[4][4];

    xr_s[t]  = g_xlr2[(size_t)node * 512 + 256 + t];
    att_s[t] = att[t];
    if (t < 4) { sm_m[t] = -1e30f; sm_d[t] = 0.f; }
    __syncthreads();

    float acc = 0.f;
    const int beg = g_offs[node], end = g_offs[node + 1];
    const float xr = xr_s[t], av = att_s[t];

    for (int k = beg; k < end; k += 4) {
        const int nv = min(4, end - k);
        float xl[4], p[4];
#pragma unroll
        for (int i = 0; i < 4; i++) {
            int kk = (k + i < end) ? k + i : k;
            int e = g_perm[kk];
            int s = g_src[e];
            xl[i] = g_xlr2[(size_t)s * 512 + t];
            float ef = g_ef2[(size_t)e * 256 + t];
            float v = xl[i] + xr + ef;
            v = v > 0.f ? v : 0.2f * v;
            p[i] = av * v;
        }
#pragma unroll
        for (int i = 0; i < 4; i++)
#pragma unroll
            for (int off = 16; off; off >>= 1)
                p[i] += __shfl_xor_sync(0xffffffffu, p[i], off);
        if (lane == 0) {
#pragma unroll
            for (int i = 0; i < 4; i++) wp[w][i] = p[i];
        }
        __syncthreads();
        if (t < 4) {
            float m = sm_m[t], d = sm_d[t];
            float sc[4], wv[4];
#pragma unroll
            for (int i = 0; i < 4; i++) {
                if (i < nv) {
                    float l = wp[2 * t][i] + wp[2 * t + 1][i];
                    float mn = fmaxf(m, l);
                    sc[i] = __expf(m - mn);
                    wv[i] = __expf(l - mn);
                    d = d * sc[i] + wv[i];
                    m = mn;
                } else { sc[i] = 1.f; wv[i] = 0.f; }
            }
            sm_m[t] = m; sm_d[t] = d;
            float s3 = sc[3], s23 = sc[2] * s3, s123 = sc[1] * s23;
            sm_S[t] = sc[0] * s123;
            sm_W[t][0] = wv[0] * s123;
            sm_W[t][1] = wv[1] * s23;
            sm_W[t][2] = wv[2] * s3;
            sm_W[t][3] = wv[3];
        }
        __syncthreads();
        acc = acc * sm_S[h] + sm_W[h][0] * xl[0] + sm_W[h][1] * xl[1]
                            + sm_W[h][2] * xl[2] + sm_W[h][3] * xl[3];
    }

    float o = acc / (sm_d[h] + 1e-16f);
    g_h2[(size_t)node * D2 + t] = fmaxf(o + bias[t], 0.f);
}

// ---------------- MLP head ----------------
__global__ void k_mlp(const void* __restrict__ n_nodes,
                      const float* __restrict__ fc1w, const float* __restrict__ fc1b,
                      const float* __restrict__ fc2w, const float* __restrict__ fc2b,
                      float* __restrict__ out)
{
    const int b = blockIdx.x;
    const int t = threadIdx.x;  // 64
    __shared__ float master[D2];
    __shared__ int s_last;
    __shared__ float ws[2];

    if (t == 0) {
        const int* w = (const int*)n_nodes;
        bool is64 = (w[1] == 0);
        long long cum = 0;
        if (is64) {
            const long long* l = (const long long*)n_nodes;
            for (int i = 0; i <= b; i++) cum += l[i];
        } else {
            for (int i = 0; i <= b; i++) cum += w[i];
        }
        s_last = (int)cum - 1;
    }
    __syncthreads();
    const int node = s_last;
    for (int i = t; i < D2; i += 64) master[i] = g_h2[(size_t)node * D2 + i];
    __syncthreads();

    float z = fc1b[t];
    for (int c = 0; c < D2; c++) z += master[c] * fc1w[c * 64 + t];
    z = fmaxf(z, 0.f);
    float v = z * fc2w[t];
#pragma unroll
    for (int off = 16; off; off >>= 1) v += __shfl_xor_sync(0xffffffffu, v, off);
    if ((t & 31) == 0) ws[t >> 5] = v;
    __syncthreads();
    if (t == 0) out[b] = ws[0] + ws[1] + fc2b[0];
}

// ---------------- launch ----------------
extern "C" void kernel_launch(void* const* d_in, const int* in_sizes, int n_in,
                              void* d_out, int out_size)
{
    const float* x    = (const float*)d_in[0];
    const void*  ei   = d_in[1];
    const float* ea   = (const float*)d_in[2];
    const void*  nnod = d_in[3];
    const float* Wl1  = (const float*)d_in[4];
    const float* bl1  = (const float*)d_in[5];
    const float* Wr1  = (const float*)d_in[6];
    const float* br1  = (const float*)d_in[7];
    const float* We1  = (const float*)d_in[8];
    const float* att1 = (const float*)d_in[9];
    const float* b1   = (const float*)d_in[10];
    const float* Wl2  = (const float*)d_in[11];
    const float* bl2  = (const float*)d_in[12];
    const float* Wr2  = (const float*)d_in[13];
    const float* br2  = (const float*)d_in[14];
    const float* We2  = (const float*)d_in[15];
    const float* att2 = (const float*)d_in[16];
    const float* b2   = (const float*)d_in[17];
    const float* fc1w = (const float*)d_in[18];
    const float* fc1b = (const float*)d_in[19];
    const float* fc2w = (const float*)d_in[20];
    const float* fc2b = (const float*)d_in[21];
    float* out = (float*)d_out;

    float *xlr1, *xlr2, *ef1, *ef2;
    bf16 *xh, *xlo, *eah, *eal, *h1h, *h1l, *w1h, *w1l, *w2h, *w2l;
    bf16 *we1h, *we1l, *we2h, *we2l;
    cudaGetSymbolAddress((void**)&xlr1, g_xlr1);
    cudaGetSymbolAddress((void**)&xlr2, g_xlr2);
    cudaGetSymbolAddress((void**)&ef1, g_ef1);
    cudaGetSymbolAddress((void**)&ef2, g_ef2);
    cudaGetSymbolAddress((void**)&xh,  g_xh);
    cudaGetSymbolAddress((void**)&xlo, g_xlo);
    cudaGetSymbolAddress((void**)&eah, g_eah);
    cudaGetSymbolAddress((void**)&eal, g_eal);
    cudaGetSymbolAddress((void**)&h1h, g_h1h);
    cudaGetSymbolAddress((void**)&h1l, g_h1l);
    cudaGetSymbolAddress((void**)&w1h, g_w1h); cudaGetSymbolAddress((void**)&w1l, g_w1l);
    cudaGetSymbolAddress((void**)&w2h, g_w2h); cudaGetSymbolAddress((void**)&w2l, g_w2l);
    cudaGetSymbolAddress((void**)&we1h, g_we1h); cudaGetSymbolAddress((void**)&we1l, g_we1l);
    cudaGetSymbolAddress((void**)&we2h, g_we2h); cudaGetSymbolAddress((void**)&we2l, g_we2l);

    cudaFuncSetAttribute(k_gemm_bf3,
                         cudaFuncAttributeMaxDynamicSharedMemorySize, SMEM_BYTES);

    const int TB = 256;

    // fork point
    cudaEventRecord(g_evF, 0);

    // ---- main stream: splits for layer-1 GEMM, then layer-1 GEMM ----
    k_split<<<(NN * 128 + 255) / 256, 256>>>(x, xh, xlo, NN * 128);
    k_split2<<<(128 * 1024 + 255) / 256, 256>>>(Wl1, w1h, w1l, 128, 1024, 2048, 0);
    k_split2<<<(128 * 1024 + 255) / 256, 256>>>(Wr1, w1h, w1l, 128, 1024, 2048, 1024);
    {
        dim3 g1(2048 / 128, NN / 128);
        k_gemm_bf3<<<g1, 256, SMEM_BYTES>>>(xh, xlo, w1h, w1l, bl1, br1, 1024,
                                            xlr1, NN, 128, 2048);
    }

    // ---- s1: edge-feature splits + ef GEMMs ----
    cudaStreamWaitEvent(g_s1, g_evF, 0);
    k_split<<<(EE * 16 + 255) / 256, 256, 0, g_s1>>>(ea, eah, eal, EE * 16);
    k_split<<<(16 * 1024 + 255) / 256, 256, 0, g_s1>>>(We1, we1h, we1l, 16 * 1024);
    {
        dim3 ge(1024 / 128, (EE + 127) / 128);
        k_gemm_bf3<<<ge, 256, SMEM_BYTES, g_s1>>>(eah, eal, we1h, we1l,
                                                  nullptr, nullptr, 0,
                                                  ef1, EE, 16, 1024);
    }
    cudaEventRecord(g_evJ2, g_s1);                 // ef1 ready
    k_split<<<(16 * 256 + 255) / 256, 256, 0, g_s1>>>(We2, we2h, we2l, 16 * 256);
    {
        dim3 ge(256 / 128, (EE + 127) / 128);
        k_gemm_bf3<<<ge, 256, SMEM_BYTES, g_s1>>>(eah, eal, we2h, we2l,
                                                  nullptr, nullptr, 0,
                                                  ef2, EE, 16, 256);
    }
    cudaEventRecord(g_evJ3, g_s1);                 // ef2 ready

    // ---- s2: CSR build + layer-2 weight splits ----
    cudaStreamWaitEvent(g_s2, g_evF, 0);
    k_zero<<<(NN + TB - 1) / TB, TB, 0, g_s2>>>();
    k_convert<<<(EE + TB - 1) / TB, TB, 0, g_s2>>>(ei);
    k_count<<<(EE + TB - 1) / TB, TB, 0, g_s2>>>();
    k_scanA<<<NB, 256, 0, g_s2>>>();
    k_scanB<<<1, 256, 0, g_s2>>>();
    k_scanC<<<NB, 256, 0, g_s2>>>();
    k_scatter<<<(EE + TB - 1) / TB, TB, 0, g_s2>>>();
    k_split2<<<(1024 * 256 + 255) / 256, 256, 0, g_s2>>>(Wl2, w2h, w2l, 1024, 256, 512, 0);
    k_split2<<<(1024 * 256 + 255) / 256, 256, 0, g_s2>>>(Wr2, w2h, w2l, 1024, 256, 512, 256);
    cudaEventRecord(g_evJ1, g_s2);                 // CSR + W2 ready

    // ---- main: join and continue ----
    cudaStreamWaitEvent(0, g_evJ1, 0);
    cudaStreamWaitEvent(0, g_evJ2, 0);
    k_gat1<<<NN, 256>>>(att1, b1);
    {
        dim3 g2(512 / 128, NN / 128);
        k_gemm_bf3<<<g2, 256, SMEM_BYTES>>>(h1h, h1l, w2h, w2l, bl2, br2, 256,
                                            xlr2, NN, 1024, 512);
    }
    cudaStreamWaitEvent(0, g_evJ3, 0);
    k_gat2<<<NN, 256>>>(att2, b2);

    k_mlp<<<BB, 64>>>(nnod, fc1w, fc1b, fc2w, fc2b, out);
}

// round 14
// speedup vs baseline: 1.1329x; 1.0808x over previous
#include <cuda_runtime.h>
#include <cuda_bf16.h>
#include <cstdint>
#include <math.h>

#define NN 49920
#define EE 200000
#define BB 128
#define HH 4
#define D1 1024
#define D2 256
#define NB ((NN + 255) / 256)   // 195

typedef __nv_bfloat16 bf16;

// ---------------- scratch ----------------
__device__ float g_xlr1[(size_t)NN * 2048];   // [xl1 | xr1]
__device__ float g_xlr2[(size_t)NN * 512];    // [xl2 | xr2]
__device__ float g_h2 [(size_t)NN * D2];
__device__ float g_logit1[(size_t)EE * 4];
__device__ float g_logit2[(size_t)EE * 4];

__device__ bf16 g_xh [(size_t)NN * 128],  g_xlo[(size_t)NN * 128];
__device__ bf16 g_eah[(size_t)EE * 16],   g_eal[(size_t)EE * 16];
__device__ bf16 g_h1h[(size_t)NN * D1],   g_h1l[(size_t)NN * D1];
__device__ bf16 g_w1h[128 * 2048],  g_w1l[128 * 2048];    // [Wl1 | Wr1]
__device__ bf16 g_w2h[1024 * 512],  g_w2l[1024 * 512];    // [Wl2 | Wr2]
__device__ bf16 g_we1h[16 * 1024],  g_we1l[16 * 1024];
__device__ bf16 g_we2h[16 * 256],   g_we2l[16 * 256];

__device__ int g_src[EE];
__device__ int g_dst[EE];
__device__ int g_cnt[NN];
__device__ int g_cur[NN];
__device__ int g_offs[NN + 1];
__device__ int g_perm[EE];
__device__ int g_part[256];

// ---------------- streams/events (created once pre-main) ----------------
static cudaStream_t g_s1, g_s2;
static cudaEvent_t g_evF, g_evJ1, g_evS1, g_evConv;
static struct StreamInit {
    StreamInit() {
        cudaStreamCreateWithFlags(&g_s1, cudaStreamNonBlocking);
        cudaStreamCreateWithFlags(&g_s2, cudaStreamNonBlocking);
        cudaEventCreateWithFlags(&g_evF,    cudaEventDisableTiming);
        cudaEventCreateWithFlags(&g_evJ1,   cudaEventDisableTiming);
        cudaEventCreateWithFlags(&g_evS1,   cudaEventDisableTiming);
        cudaEventCreateWithFlags(&g_evConv, cudaEventDisableTiming);
    }
} g_streamInit;

// ---------------- CSR build ----------------
__global__ void k_zero()
{
    int i = blockIdx.x * blockDim.x + threadIdx.x;
    if (i < NN) { g_cnt[i] = 0; g_cur[i] = 0; }
}

__global__ void k_zerof(float* __restrict__ p, int n)
{
    int i = blockIdx.x * blockDim.x + threadIdx.x;
    if (i < n) p[i] = 0.f;
}

__global__ void k_convert(const void* __restrict__ ei)
{
    int e = blockIdx.x * blockDim.x + threadIdx.x;
    if (e >= EE) return;
    const int* w = (const int*)ei;
    bool is64 = true;
#pragma unroll
    for (int i = 1; i < 16; i += 2) is64 = is64 && (w[i] == 0);
    if (is64) {
        const long long* l = (const long long*)ei;
        g_src[e] = (int)l[e];
        g_dst[e] = (int)l[(size_t)EE + e];
    } else {
        g_src[e] = w[e];
        g_dst[e] = w[EE + e];
    }
}

__global__ void k_count()
{
    int e = blockIdx.x * blockDim.x + threadIdx.x;
    if (e < EE) atomicAdd(&g_cnt[g_dst[e]], 1);
}

__global__ void k_scanA()
{
    __shared__ int sw[8];
    int t = threadIdx.x;
    int i = blockIdx.x * 256 + t;
    int v = (i < NN) ? g_cnt[i] : 0;
#pragma unroll
    for (int off = 16; off; off >>= 1) v += __shfl_xor_sync(0xffffffffu, v, off);
    if ((t & 31) == 0) sw[t >> 5] = v;
    __syncthreads();
    if (t == 0) {
        int s = 0;
#pragma unroll
        for (int j = 0; j < 8; j++) s += sw[j];
        g_part[blockIdx.x] = s;
    }
}

__global__ void k_scanB()
{
    __shared__ int s[256];
    int t = threadIdx.x;
    int v = (t < NB) ? g_part[t] : 0;
    s[t] = v;
    __syncthreads();
    for (int off = 1; off < 256; off <<= 1) {
        int add = (t >= off) ? s[t - off] : 0;
        __syncthreads();
        s[t] += add;
        __syncthreads();
    }
    g_part[t] = s[t] - v;
}

__global__ void k_scanC()
{
    __shared__ int s[256];
    int t = threadIdx.x;
    int i = blockIdx.x * 256 + t;
    int v = (i < NN) ? g_cnt[i] : 0;
    s[t] = v;
    __syncthreads();
    for (int off = 1; off < 256; off <<= 1) {
        int add = (t >= off) ? s[t - off] : 0;
        __syncthreads();
        s[t] += add;
        __syncthreads();
    }
    if (i < NN) g_offs[i] = g_part[blockIdx.x] + s[t] - v;
    if (i == NN - 1) g_offs[NN] = EE;
}

__global__ void k_scatter()
{
    int e = blockIdx.x * blockDim.x + threadIdx.x;
    if (e >= EE) return;
    int d = g_dst[e];
    int p = g_offs[d] + atomicAdd(&g_cur[d], 1);
    g_perm[p] = e;
}

// ---------------- bf16 hi/lo split ----------------
__global__ void k_split(const float* __restrict__ src, bf16* __restrict__ hi,
                        bf16* __restrict__ lo, int n)
{
    int i = blockIdx.x * blockDim.x + threadIdx.x;
    if (i >= n) return;
    float v = src[i];
    bf16 h = __float2bfloat16_rn(v);
    hi[i] = h;
    lo[i] = __float2bfloat16_rn(v - __bfloat162float(h));
}

__global__ void k_split2(const float* __restrict__ src, bf16* __restrict__ hi,
                         bf16* __restrict__ lo, int K, int Nsrc, int Ndst, int coff)
{
    int i = blockIdx.x * blockDim.x + threadIdx.x;
    if (i >= K * Nsrc) return;
    int r = i / Nsrc, c = i % Nsrc;
    float v = src[i];
    bf16 h = __float2bfloat16_rn(v);
    size_t o = (size_t)r * Ndst + coff + c;
    hi[o] = h;
    lo[o] = __float2bfloat16_rn(v - __bfloat162float(h));
}

// ---------------- shared GEMM machinery ----------------
#define AST 40
#define BST 136
#define A_HALF (128 * AST)
#define B_HALF (32 * BST)
#define STAGE_ELEMS (2 * A_HALF + 2 * B_HALF)
#define SMEM_BYTES (2 * STAGE_ELEMS * 2)

__device__ __forceinline__ void cpa16(unsigned dst, const void* src, int sz)
{
    asm volatile("cp.async.cg.shared.global [%0], [%1], 16, %2;\n"
                 :: "r"(dst), "l"(src), "r"(sz));
}
__device__ __forceinline__ void ldsm_x4(unsigned* r, unsigned a)
{
    asm volatile("ldmatrix.sync.aligned.m8n8.x4.shared.b16 {%0,%1,%2,%3}, [%4];\n"
                 : "=r"(r[0]), "=r"(r[1]), "=r"(r[2]), "=r"(r[3]) : "r"(a));
}
__device__ __forceinline__ void ldsm_x2t(unsigned* r, unsigned a)
{
    asm volatile("ldmatrix.sync.aligned.m8n8.x2.trans.shared.b16 {%0,%1}, [%2];\n"
                 : "=r"(r[0]), "=r"(r[1]) : "r"(a));
}
__device__ __forceinline__ void mma16816(float* d, const unsigned* a, const unsigned* b)
{
    asm volatile(
        "mma.sync.aligned.m16n8k16.row.col.f32.bf16.bf16.f32 "
        "{%0,%1,%2,%3}, {%4,%5,%6,%7}, {%8,%9}, {%0,%1,%2,%3};\n"
        : "+f"(d[0]), "+f"(d[1]), "+f"(d[2]), "+f"(d[3])
        : "r"(a[0]), "r"(a[1]), "r"(a[2]), "r"(a[3]), "r"(b[0]), "r"(b[1]));
}

// mainloop macro: fills acc[2][8][4] for block tile (m0,n0)
#define GEMM_MAINLOOP(Ah, Al, Bh, Bl, M, K, Ncol)                                  \
    float acc[2][8][4];                                                            \
    _Pragma("unroll") for (int i = 0; i < 2; i++)                                  \
        _Pragma("unroll") for (int j = 0; j < 8; j++)                              \
            _Pragma("unroll") for (int r = 0; r < 4; r++) acc[i][j][r] = 0.f;      \
    const int T = (K + 31) / 32;                                                   \
    auto load_stage = [&](int it) {                                                \
        const int k0 = it * 32;                                                    \
        bf16* S = smem + (it & 1) * STAGE_ELEMS;                                   \
        _Pragma("unroll") for (int q = 0; q < 4; q++) {                            \
            int f = tid + q * 256;                                                 \
            int hl = f >> 9;                                                       \
            int r = (f >> 2) & 127;                                                \
            int ck = (f & 3) * 8;                                                  \
            const bf16* srcp = hl ? Al : Ah;                                       \
            bool ok = (m0 + r < M) && (k0 + ck < K);                               \
            const bf16* sp = ok ? (srcp + (size_t)(m0 + r) * K + k0 + ck) : srcp;  \
            bf16* dp = S + hl * A_HALF + r * AST + ck;                             \
            cpa16((unsigned)__cvta_generic_to_shared(dp), sp, ok ? 16 : 0);        \
        }                                                                          \
        _Pragma("unroll") for (int q = 0; q < 4; q++) {                            \
            int f = tid + q * 256;                                                 \
            int hl = f >> 9;                                                       \
            int r = (f >> 4) & 31;                                                 \
            int cn = (f & 15) * 8;                                                 \
            const bf16* srcp = hl ? Bl : Bh;                                       \
            bool ok = (k0 + r < K);                                                \
            const bf16* sp = ok ? (srcp + (size_t)(k0 + r) * Ncol + n0 + cn) : srcp;\
            bf16* dp = S + 2 * A_HALF + hl * B_HALF + r * BST + cn;                \
            cpa16((unsigned)__cvta_generic_to_shared(dp), sp, ok ? 16 : 0);        \
        }                                                                          \
        asm volatile("cp.async.commit_group;\n");                                  \
    };                                                                             \
    load_stage(0);                                                                 \
    for (int it = 0; it < T; it++) {                                               \
        if (it + 1 < T) {                                                          \
            load_stage(it + 1);                                                    \
            asm volatile("cp.async.wait_group 1;\n");                              \
        } else {                                                                   \
            asm volatile("cp.async.wait_group 0;\n");                              \
        }                                                                          \
        __syncthreads();                                                           \
        const bf16* S = smem + (it & 1) * STAGE_ELEMS;                             \
        const bf16* sAh = S;                                                       \
        const bf16* sAl = S + A_HALF;                                              \
        const bf16* sBh = S + 2 * A_HALF;                                          \
        const bf16* sBl = S + 2 * A_HALF + B_HALF;                                 \
        _Pragma("unroll") for (int ks = 0; ks < 32; ks += 16) {                    \
            unsigned aFh[2][4], aFl[2][4];                                         \
            _Pragma("unroll") for (int mt = 0; mt < 2; mt++) {                     \
                int row = wm * 32 + mt * 16 + (lane & 7) + ((lane >> 3) & 1) * 8;  \
                int col = ks + (lane >> 4) * 8;                                    \
                ldsm_x4(aFh[mt], (unsigned)__cvta_generic_to_shared(sAh + row * AST + col)); \
                ldsm_x4(aFl[mt], (unsigned)__cvta_generic_to_shared(sAl + row * AST + col)); \
            }                                                                      \
            _Pragma("unroll") for (int nt = 0; nt < 8; nt++) {                     \
                int brow = ks + (lane & 15);                                       \
                int bcol = wn * 64 + nt * 8;                                       \
                unsigned bFh[2], bFl[2];                                           \
                ldsm_x2t(bFh, (unsigned)__cvta_generic_to_shared(sBh + brow * BST + bcol)); \
                ldsm_x2t(bFl, (unsigned)__cvta_generic_to_shared(sBl + brow * BST + bcol)); \
                _Pragma("unroll") for (int mt = 0; mt < 2; mt++) {                 \
                    mma16816(acc[mt][nt], aFh[mt], bFh);                           \
                    mma16816(acc[mt][nt], aFl[mt], bFh);                           \
                    mma16816(acc[mt][nt], aFh[mt], bFl);                           \
                }                                                                  \
            }                                                                      \
        }                                                                          \
        __syncthreads();                                                           \
    }

// ---------------- GEMM with C output (node projections) ----------------
__global__ __launch_bounds__(256, 2) void k_gemm_bf3(const bf16* __restrict__ Ah,
                                                     const bf16* __restrict__ Al,
                                                     const bf16* __restrict__ Bh,
                                                     const bf16* __restrict__ Bl,
                                                     const float* __restrict__ biasA,
                                                     const float* __restrict__ biasB,
                                                     int nsplit,
                                                     float* __restrict__ C,
                                                     int M, int K, int Ncol)
{
    extern __shared__ bf16 smem[];
    const int tid = threadIdx.x;
    const int lane = tid & 31, w = tid >> 5;
    const int wm = w & 3, wn = w >> 2;
    const int m0 = blockIdx.y * 128, n0 = blockIdx.x * 128;

    GEMM_MAINLOOP(Ah, Al, Bh, Bl, M, K, Ncol)

    auto bget = [&](int c) -> float {
        if (!biasA) return 0.f;
        return (c < nsplit) ? __ldg(biasA + c) : __ldg(biasB + c - nsplit);
    };

#pragma unroll
    for (int mt = 0; mt < 2; mt++) {
#pragma unroll
        for (int nt = 0; nt < 8; nt++) {
            int r = m0 + wm * 32 + mt * 16 + (lane >> 2);
            int c = n0 + wn * 64 + nt * 8 + (lane & 3) * 2;
            float b0 = bget(c), b1 = bget(c + 1);
            if (r < M)
                *(float2*)(C + (size_t)r * Ncol + c) =
                    make_float2(acc[mt][nt][0] + b0, acc[mt][nt][1] + b1);
            if (r + 8 < M)
                *(float2*)(C + (size_t)(r + 8) * Ncol + c) =
                    make_float2(acc[mt][nt][2] + b0, acc[mt][nt][3] + b1);
        }
    }
}

// ---------------- ef GEMM with fused logit epilogue ----------------
// A rows = edges; epilogue: logit[e][head] += sum_c att[c]*leaky(xl[src]+xr[dst]+ef)
__global__ __launch_bounds__(256, 2) void k_gemm_logit(const bf16* __restrict__ Ah,
                                                       const bf16* __restrict__ Al,
                                                       const bf16* __restrict__ Bh,
                                                       const bf16* __restrict__ Bl,
                                                       const float* __restrict__ att,
                                                       const float* __restrict__ xlr,
                                                       int rstride, int half,
                                                       float* __restrict__ logitOut,
                                                       int headShift,
                                                       int M, int K, int Ncol)
{
    extern __shared__ bf16 smem[];
    const int tid = threadIdx.x;
    const int lane = tid & 31, w = tid >> 5;
    const int wm = w & 3, wn = w >> 2;
    const int m0 = blockIdx.y * 128, n0 = blockIdx.x * 128;

    GEMM_MAINLOOP(Ah, Al, Bh, Bl, M, K, Ncol)

    // logit epilogue
    const int head = (n0 + wn * 64) >> headShift;
    float pl[2][2];
#pragma unroll
    for (int mt = 0; mt < 2; mt++) {
#pragma unroll
        for (int rh = 0; rh < 2; rh++) {
            pl[mt][rh] = 0.f;
            int r = m0 + wm * 32 + mt * 16 + (lane >> 2) + rh * 8;
            if (r >= M) continue;
            int s = g_src[r], dd = g_dst[r];
            const float* xlrow = xlr + (size_t)s * rstride;
            const float* xrrow = xlr + (size_t)dd * rstride + half;
            float sum = 0.f;
#pragma unroll
            for (int nt = 0; nt < 8; nt++) {
                int c = n0 + wn * 64 + nt * 8 + (lane & 3) * 2;
                float2 xlv = *(const float2*)(xlrow + c);
                float2 xrv = *(const float2*)(xrrow + c);
                float a0 = __ldg(att + c), a1 = __ldg(att + c + 1);
                float v0 = acc[mt][nt][rh * 2 + 0] + xlv.x + xrv.x;
                float v1 = acc[mt][nt][rh * 2 + 1] + xlv.y + xrv.y;
                v0 = v0 > 0.f ? v0 : 0.2f * v0;
                v1 = v1 > 0.f ? v1 : 0.2f * v1;
                sum += a0 * v0 + a1 * v1;
            }
            pl[mt][rh] = sum;
        }
    }
#pragma unroll
    for (int mt = 0; mt < 2; mt++)
#pragma unroll
        for (int rh = 0; rh < 2; rh++) {
            pl[mt][rh] += __shfl_xor_sync(0xffffffffu, pl[mt][rh], 1);
            pl[mt][rh] += __shfl_xor_sync(0xffffffffu, pl[mt][rh], 2);
        }
    if ((lane & 3) == 0) {
#pragma unroll
        for (int mt = 0; mt < 2; mt++)
#pragma unroll
            for (int rh = 0; rh < 2; rh++) {
                int r = m0 + wm * 32 + mt * 16 + (lane >> 2) + rh * 8;
                if (r < M) atomicAdd(logitOut + (size_t)r * 4 + head, pl[mt][rh]);
            }
    }
}

// ---------------- fused GATv2 layer 1 (sync-free, logits precomputed) ----------------
// thread t owns channels [4t, 4t+4); head = t>>6
__global__ __launch_bounds__(256) void k_gat1(const float* __restrict__ bias)
{
    const int node = blockIdx.x;
    const int t = threadIdx.x;
    const int c0 = t * 4;
    const int h = t >> 6;

    float m = -1e30f, d = 0.f;
    float4 acc = make_float4(0.f, 0.f, 0.f, 0.f);
    const int beg = g_offs[node], end = g_offs[node + 1];

    for (int k = beg; k < end; k++) {
        const int e = g_perm[k];
        const int s = g_src[e];
        float lg = __ldg(g_logit1 + (size_t)e * 4 + h);
        float4 xl = *(const float4*)(g_xlr1 + (size_t)s * 2048 + c0);
        float mn = fmaxf(m, lg);
        float sc = __expf(m - mn), wv = __expf(lg - mn);
        d = d * sc + wv;
        acc.x = acc.x * sc + wv * xl.x;
        acc.y = acc.y * sc + wv * xl.y;
        acc.z = acc.z * sc + wv * xl.z;
        acc.w = acc.w * sc + wv * xl.w;
        m = mn;
    }

    float inv = 1.f / (d + 1e-16f);
    float4 bv = *(const float4*)(bias + c0);
    float o0 = fmaxf(acc.x * inv + bv.x, 0.f);
    float o1 = fmaxf(acc.y * inv + bv.y, 0.f);
    float o2 = fmaxf(acc.z * inv + bv.z, 0.f);
    float o3 = fmaxf(acc.w * inv + bv.w, 0.f);
    bf16 h0 = __float2bfloat16_rn(o0), h1v = __float2bfloat16_rn(o1);
    bf16 h2 = __float2bfloat16_rn(o2), h3 = __float2bfloat16_rn(o3);
    bf16* ph = g_h1h + (size_t)node * D1 + c0;
    bf16* pl = g_h1l + (size_t)node * D1 + c0;
    ph[0] = h0; ph[1] = h1v; ph[2] = h2; ph[3] = h3;
    pl[0] = __float2bfloat16_rn(o0 - __bfloat162float(h0));
    pl[1] = __float2bfloat16_rn(o1 - __bfloat162float(h1v));
    pl[2] = __float2bfloat16_rn(o2 - __bfloat162float(h2));
    pl[3] = __float2bfloat16_rn(o3 - __bfloat162float(h3));
}

// ---------------- fused GATv2 layer 2 (sync-free) ----------------
__global__ __launch_bounds__(256) void k_gat2(const float* __restrict__ bias)
{
    const int node = blockIdx.x;
    const int t = threadIdx.x;
    const int h = t >> 6;

    float m = -1e30f, d = 0.f, acc = 0.f;
    const int beg = g_offs[node], end = g_offs[node + 1];

    for (int k = beg; k < end; k++) {
        const int e = g_perm[k];
        const int s = g_src[e];
        float lg = __ldg(g_logit2 + (size_t)e * 4 + h);
        float xl = g_xlr2[(size_t)s * 512 + t];
        float mn = fmaxf(m, lg);
        float sc = __expf(m - mn), wv = __expf(lg - mn);
        d = d * sc + wv;
        acc = acc * sc + wv * xl;
        m = mn;
    }

    float o = acc / (d + 1e-16f);
    g_h2[(size_t)node * D2 + t] = fmaxf(o + bias[t], 0.f);
}

// ---------------- MLP head ----------------
__global__ void k_mlp(const void* __restrict__ n_nodes,
                      const float* __restrict__ fc1w, const float* __restrict__ fc1b,
                      const float* __restrict__ fc2w, const float* __restrict__ fc2b,
                      float* __restrict__ out)
{
    const int b = blockIdx.x;
    const int t = threadIdx.x;  // 64
    __shared__ float master[D2];
    __shared__ int s_last;
    __shared__ float ws[2];

    if (t == 0) {
        const int* w = (const int*)n_nodes;
        bool is64 = (w[1] == 0);
        long long cum = 0;
        if (is64) {
            const long long* l = (const long long*)n_nodes;
            for (int i = 0; i <= b; i++) cum += l[i];
        } else {
            for (int i = 0; i <= b; i++) cum += w[i];
        }
        s_last = (int)cum - 1;
    }
    __syncthreads();
    const int node = s_last;
    for (int i = t; i < D2; i += 64) master[i] = g_h2[(size_t)node * D2 + i];
    __syncthreads();

    float z = fc1b[t];
    for (int c = 0; c < D2; c++) z += master[c] * fc1w[c * 64 + t];
    z = fmaxf(z, 0.f);
    float v = z * fc2w[t];
#pragma unroll
    for (int off = 16; off; off >>= 1) v += __shfl_xor_sync(0xffffffffu, v, off);
    if ((t & 31) == 0) ws[t >> 5] = v;
    __syncthreads();
    if (t == 0) out[b] = ws[0] + ws[1] + fc2b[0];
}

// ---------------- launch ----------------
extern "C" void kernel_launch(void* const* d_in, const int* in_sizes, int n_in,
                              void* d_out, int out_size)
{
    const float* x    = (const float*)d_in[0];
    const void*  ei   = d_in[1];
    const float* ea   = (const float*)d_in[2];
    const void*  nnod = d_in[3];
    const float* Wl1  = (const float*)d_in[4];
    const float* bl1  = (const float*)d_in[5];
    const float* Wr1  = (const float*)d_in[6];
    const float* br1  = (const float*)d_in[7];
    const float* We1  = (const float*)d_in[8];
    const float* att1 = (const float*)d_in[9];
    const float* b1   = (const float*)d_in[10];
    const float* Wl2  = (const float*)d_in[11];
    const float* bl2  = (const float*)d_in[12];
    const float* Wr2  = (const float*)d_in[13];
    const float* br2  = (const float*)d_in[14];
    const float* We2  = (const float*)d_in[15];
    const float* att2 = (const float*)d_in[16];
    const float* b2   = (const float*)d_in[17];
    const float* fc1w = (const float*)d_in[18];
    const float* fc1b = (const float*)d_in[19];
    const float* fc2w = (const float*)d_in[20];
    const float* fc2b = (const float*)d_in[21];
    float* out = (float*)d_out;

    float *xlr1, *xlr2, *lg1, *lg2;
    bf16 *xh, *xlo, *eah, *eal, *h1h, *h1l, *w1h, *w1l, *w2h, *w2l;
    bf16 *we1h, *we1l, *we2h, *we2l;
    cudaGetSymbolAddress((void**)&xlr1, g_xlr1);
    cudaGetSymbolAddress((void**)&xlr2, g_xlr2);
    cudaGetSymbolAddress((void**)&lg1, g_logit1);
    cudaGetSymbolAddress((void**)&lg2, g_logit2);
    cudaGetSymbolAddress((void**)&xh,  g_xh);
    cudaGetSymbolAddress((void**)&xlo, g_xlo);
    cudaGetSymbolAddress((void**)&eah, g_eah);
    cudaGetSymbolAddress((void**)&eal, g_eal);
    cudaGetSymbolAddress((void**)&h1h, g_h1h);
    cudaGetSymbolAddress((void**)&h1l, g_h1l);
    cudaGetSymbolAddress((void**)&w1h, g_w1h); cudaGetSymbolAddress((void**)&w1l, g_w1l);
    cudaGetSymbolAddress((void**)&w2h, g_w2h); cudaGetSymbolAddress((void**)&w2l, g_w2l);
    cudaGetSymbolAddress((void**)&we1h, g_we1h); cudaGetSymbolAddress((void**)&we1l, g_we1l);
    cudaGetSymbolAddress((void**)&we2h, g_we2h); cudaGetSymbolAddress((void**)&we2l, g_we2l);

    cudaFuncSetAttribute(k_gemm_bf3,
                         cudaFuncAttributeMaxDynamicSharedMemorySize, SMEM_BYTES);
    cudaFuncSetAttribute(k_gemm_logit,
                         cudaFuncAttributeMaxDynamicSharedMemorySize, SMEM_BYTES);

    const int TB = 256;

    // fork
    cudaEventRecord(g_evF, 0);

    // ---- s2: CSR build + layer-2 weight splits ----
    cudaStreamWaitEvent(g_s2, g_evF, 0);
    k_zero<<<(NN + TB - 1) / TB, TB, 0, g_s2>>>();
    k_convert<<<(EE + TB - 1) / TB, TB, 0, g_s2>>>(ei);
    cudaEventRecord(g_evConv, g_s2);
    k_count<<<(EE + TB - 1) / TB, TB, 0, g_s2>>>();
    k_scanA<<<NB, 256, 0, g_s2>>>();
    k_scanB<<<1, 256, 0, g_s2>>>();
    k_scanC<<<NB, 256, 0, g_s2>>>();
    k_scatter<<<(EE + TB - 1) / TB, TB, 0, g_s2>>>();
    k_split2<<<(1024 * 256 + 255) / 256, 256, 0, g_s2>>>(Wl2, w2h, w2l, 1024, 256, 512, 0);
    k_split2<<<(1024 * 256 + 255) / 256, 256, 0, g_s2>>>(Wr2, w2h, w2l, 1024, 256, 512, 256);
    cudaEventRecord(g_evJ1, g_s2);

    // ---- s1: logit zero + edge/We splits ----
    cudaStreamWaitEvent(g_s1, g_evF, 0);
    k_zerof<<<(EE * 4 + 255) / 256, 256, 0, g_s1>>>(lg1, EE * 4);
    k_zerof<<<(EE * 4 + 255) / 256, 256, 0, g_s1>>>(lg2, EE * 4);
    k_split<<<(EE * 16 + 255) / 256, 256, 0, g_s1>>>(ea, eah, eal, EE * 16);
    k_split<<<(16 * 1024 + 255) / 256, 256, 0, g_s1>>>(We1, we1h, we1l, 16 * 1024);
    k_split<<<(16 * 256 + 255) / 256, 256, 0, g_s1>>>(We2, we2h, we2l, 16 * 256);
    cudaEventRecord(g_evS1, g_s1);

    // ---- main: node splits + layer-1 GEMM ----
    k_split<<<(NN * 128 + 255) / 256, 256>>>(x, xh, xlo, NN * 128);
    k_split2<<<(128 * 1024 + 255) / 256, 256>>>(Wl1, w1h, w1l, 128, 1024, 2048, 0);
    k_split2<<<(128 * 1024 + 255) / 256, 256>>>(Wr1, w1h, w1l, 128, 1024, 2048, 1024);
    {
        dim3 g1(2048 / 128, NN / 128);
        k_gemm_bf3<<<g1, 256, SMEM_BYTES>>>(xh, xlo, w1h, w1l, bl1, br1, 1024,
                                            xlr1, NN, 128, 2048);
    }

    // ---- main: edge-logit GEMM layer 1 (needs xlr1, src/dst, ea splits, zeroed logits) ----
    cudaStreamWaitEvent(0, g_evConv, 0);
    cudaStreamWaitEvent(0, g_evS1, 0);
    {
        dim3 ge(1024 / 128, (EE + 127) / 128);
        k_gemm_logit<<<ge, 256, SMEM_BYTES>>>(eah, eal, we1h, we1l, att1,
                                              xlr1, 2048, 1024, lg1, 8,
                                              EE, 16, 1024);
    }

    // ---- main: gat1 (needs CSR), layer-2 GEMM, edge-logit 2, gat2, mlp ----
    cudaStreamWaitEvent(0, g_evJ1, 0);
    k_gat1<<<NN, 256>>>(b1);
    {
        dim3 g2(512 / 128, NN / 128);
        k_gemm_bf3<<<g2, 256, SMEM_BYTES>>>(h1h, h1l, w2h, w2l, bl2, br2, 256,
                                            xlr2, NN, 1024, 512);
    }
    {
        dim3 ge(256 / 128, (EE + 127) / 128);
        k_gemm_logit<<<ge, 256, SMEM_BYTES>>>(eah, eal, we2h, we2l, att2,
                                              xlr2, 512, 256, lg2, 6,
                                              EE, 16, 256);
    }
    k_gat2<<<NN, 256>>>(b2);

    k_mlp<<<BB, 64>>>(nnod, fc1w, fc1b, fc2w, fc2b, out);
}

// round 17
// speedup vs baseline: 1.1437x; 1.0095x over previous
#include <cuda_runtime.h>
#include <cuda_bf16.h>
#include <cstdint>
#include <math.h>

#define NN 49920
#define EE 200000
#define BB 128
#define HH 4
#define D1 1024
#define D2 256
#define NB ((NN + 255) / 256)   // 195

typedef __nv_bfloat16 bf16;

// ---------------- scratch ----------------
__device__ float g_xlr1[(size_t)NN * 2048];   // [xl1 | xr1]
__device__ float g_xlr2[(size_t)NN * 512];    // [xl2 | xr2]
__device__ float g_h2 [(size_t)NN * D2];
__device__ float g_logit1[(size_t)EE * 4];
__device__ float g_logit2[(size_t)EE * 4];

__device__ bf16 g_xh [(size_t)NN * 128],  g_xlo[(size_t)NN * 128];
__device__ bf16 g_eah[(size_t)EE * 16],   g_eal[(size_t)EE * 16];
__device__ bf16 g_h1h[(size_t)NN * D1],   g_h1l[(size_t)NN * D1];
__device__ bf16 g_w1h[128 * 2048],  g_w1l[128 * 2048];    // [Wl1 | Wr1]
__device__ bf16 g_w2h[1024 * 512],  g_w2l[1024 * 512];    // [Wl2 | Wr2]
__device__ bf16 g_we1h[16 * 1024],  g_we1l[16 * 1024];
__device__ bf16 g_we2h[16 * 256],   g_we2l[16 * 256];

__device__ int g_src[EE];
__device__ int g_dst[EE];
__device__ int g_cnt[NN];
__device__ int g_cur[NN];
__device__ int g_offs[NN + 1];
__device__ int g_perm[EE];
__device__ int g_part[256];

// ---------------- streams/events ----------------
static cudaStream_t g_s1, g_s2;
static cudaEvent_t g_evF, g_evJ1, g_evS1, g_evConv;
static struct StreamInit {
    StreamInit() {
        cudaStreamCreateWithFlags(&g_s1, cudaStreamNonBlocking);
        cudaStreamCreateWithFlags(&g_s2, cudaStreamNonBlocking);
        cudaEventCreateWithFlags(&g_evF,    cudaEventDisableTiming);
        cudaEventCreateWithFlags(&g_evJ1,   cudaEventDisableTiming);
        cudaEventCreateWithFlags(&g_evS1,   cudaEventDisableTiming);
        cudaEventCreateWithFlags(&g_evConv, cudaEventDisableTiming);
    }
} g_streamInit;

// ---------------- CSR build ----------------
__global__ void k_zero()
{
    int i = blockIdx.x * blockDim.x + threadIdx.x;
    if (i < NN) { g_cnt[i] = 0; g_cur[i] = 0; }
}

__global__ void k_zerof(float* __restrict__ p, int n)
{
    int i = blockIdx.x * blockDim.x + threadIdx.x;
    if (i < n) p[i] = 0.f;
}

__global__ void k_convert(const void* __restrict__ ei)
{
    int e = blockIdx.x * blockDim.x + threadIdx.x;
    if (e >= EE) return;
    const int* w = (const int*)ei;
    bool is64 = true;
#pragma unroll
    for (int i = 1; i < 16; i += 2) is64 = is64 && (w[i] == 0);
    if (is64) {
        const long long* l = (const long long*)ei;
        g_src[e] = (int)l[e];
        g_dst[e] = (int)l[(size_t)EE + e];
    } else {
        g_src[e] = w[e];
        g_dst[e] = w[EE + e];
    }
}

__global__ void k_count()
{
    int e = blockIdx.x * blockDim.x + threadIdx.x;
    if (e < EE) atomicAdd(&g_cnt[g_dst[e]], 1);
}

__global__ void k_scanA()
{
    __shared__ int sw[8];
    int t = threadIdx.x;
    int i = blockIdx.x * 256 + t;
    int v = (i < NN) ? g_cnt[i] : 0;
#pragma unroll
    for (int off = 16; off; off >>= 1) v += __shfl_xor_sync(0xffffffffu, v, off);
    if ((t & 31) == 0) sw[t >> 5] = v;
    __syncthreads();
    if (t == 0) {
        int s = 0;
#pragma unroll
        for (int j = 0; j < 8; j++) s += sw[j];
        g_part[blockIdx.x] = s;
    }
}

__global__ void k_scanB()
{
    __shared__ int s[256];
    int t = threadIdx.x;
    int v = (t < NB) ? g_part[t] : 0;
    s[t] = v;
    __syncthreads();
    for (int off = 1; off < 256; off <<= 1) {
        int add = (t >= off) ? s[t - off] : 0;
        __syncthreads();
        s[t] += add;
        __syncthreads();
    }
    g_part[t] = s[t] - v;
}

__global__ void k_scanC()
{
    __shared__ int s[256];
    int t = threadIdx.x;
    int i = blockIdx.x * 256 + t;
    int v = (i < NN) ? g_cnt[i] : 0;
    s[t] = v;
    __syncthreads();
    for (int off = 1; off < 256; off <<= 1) {
        int add = (t >= off) ? s[t - off] : 0;
        __syncthreads();
        s[t] += add;
        __syncthreads();
    }
    if (i < NN) g_offs[i] = g_part[blockIdx.x] + s[t] - v;
    if (i == NN - 1) g_offs[NN] = EE;
}

__global__ void k_scatter()
{
    int e = blockIdx.x * blockDim.x + threadIdx.x;
    if (e >= EE) return;
    int d = g_dst[e];
    int p = g_offs[d] + atomicAdd(&g_cur[d], 1);
    g_perm[p] = e;
}

// ---------------- bf16 hi/lo split ----------------
__global__ void k_split(const float* __restrict__ src, bf16* __restrict__ hi,
                        bf16* __restrict__ lo, int n)
{
    int i = blockIdx.x * blockDim.x + threadIdx.x;
    if (i >= n) return;
    float v = src[i];
    bf16 h = __float2bfloat16_rn(v);
    hi[i] = h;
    lo[i] = __float2bfloat16_rn(v - __bfloat162float(h));
}

__global__ void k_split2(const float* __restrict__ src, bf16* __restrict__ hi,
                         bf16* __restrict__ lo, int K, int Nsrc, int Ndst, int coff)
{
    int i = blockIdx.x * blockDim.x + threadIdx.x;
    if (i >= K * Nsrc) return;
    int r = i / Nsrc, c = i % Nsrc;
    float v = src[i];
    bf16 h = __float2bfloat16_rn(v);
    size_t o = (size_t)r * Ndst + coff + c;
    hi[o] = h;
    lo[o] = __float2bfloat16_rn(v - __bfloat162float(h));
}

// ---------------- GEMM machinery ----------------
#define AST 40
#define BST 136
#define A_HALF (128 * AST)
#define B_HALF (32 * BST)
#define STAGE_ELEMS (2 * A_HALF + 2 * B_HALF)
#define SMEM_BYTES (2 * STAGE_ELEMS * 2)

__device__ __forceinline__ void cpa16(unsigned dst, const void* src, int sz)
{
    asm volatile("cp.async.cg.shared.global [%0], [%1], 16, %2;\n"
                 :: "r"(dst), "l"(src), "r"(sz));
}
__device__ __forceinline__ void ldsm_x4(unsigned* r, unsigned a)
{
    asm volatile("ldmatrix.sync.aligned.m8n8.x4.shared.b16 {%0,%1,%2,%3}, [%4];\n"
                 : "=r"(r[0]), "=r"(r[1]), "=r"(r[2]), "=r"(r[3]) : "r"(a));
}
__device__ __forceinline__ void ldsm_x2t(unsigned* r, unsigned a)
{
    asm volatile("ldmatrix.sync.aligned.m8n8.x2.trans.shared.b16 {%0,%1}, [%2];\n"
                 : "=r"(r[0]), "=r"(r[1]) : "r"(a));
}
__device__ __forceinline__ void mma16816(float* d, const unsigned* a, const unsigned* b)
{
    asm volatile(
        "mma.sync.aligned.m16n8k16.row.col.f32.bf16.bf16.f32 "
        "{%0,%1,%2,%3}, {%4,%5,%6,%7}, {%8,%9}, {%0,%1,%2,%3};\n"
        : "+f"(d[0]), "+f"(d[1]), "+f"(d[2]), "+f"(d[3])
        : "r"(a[0]), "r"(a[1]), "r"(a[2]), "r"(a[3]), "r"(b[0]), "r"(b[1]));
}

// mainloop: fills acc[2][8][4] for block tile (m0,n0). bf16x3 compensated.
// ks loop skips the k=16..31 half-step when the tail has <= 16 valid k (zeros).
#define GEMM_MAINLOOP(Ah, Al, Bh, Bl, M, K, Ncol)                                  \
    float acc[2][8][4];                                                            \
    _Pragma("unroll") for (int i = 0; i < 2; i++)                                  \
        _Pragma("unroll") for (int j = 0; j < 8; j++)                              \
            _Pragma("unroll") for (int r = 0; r < 4; r++) acc[i][j][r] = 0.f;      \
    const int T = (K + 31) / 32;                                                   \
    auto load_stage = [&](int it) {                                                \
        const int k0 = it * 32;                                                    \
        bf16* S = smem + (it & 1) * STAGE_ELEMS;                                   \
        _Pragma("unroll") for (int q = 0; q < 4; q++) {                            \
            int f = tid + q * 256;                                                 \
            int hl = f >> 9;                                                       \
            int r = (f >> 2) & 127;                                                \
            int ck = (f & 3) * 8;                                                  \
            const bf16* srcp = hl ? Al : Ah;                                       \
            bool ok = (m0 + r < M) && (k0 + ck < K);                               \
            const bf16* sp = ok ? (srcp + (size_t)(m0 + r) * K + k0 + ck) : srcp;  \
            bf16* dp = S + hl * A_HALF + r * AST + ck;                             \
            cpa16((unsigned)__cvta_generic_to_shared(dp), sp, ok ? 16 : 0);        \
        }                                                                          \
        _Pragma("unroll") for (int q = 0; q < 4; q++) {                            \
            int f = tid + q * 256;                                                 \
            int hl = f >> 9;                                                       \
            int r = (f >> 4) & 31;                                                 \
            int cn = (f & 15) * 8;                                                 \
            const bf16* srcp = hl ? Bl : Bh;                                       \
            bool ok = (k0 + r < K);                                                \
            const bf16* sp = ok ? (srcp + (size_t)(k0 + r) * Ncol + n0 + cn) : srcp;\
            bf16* dp = S + 2 * A_HALF + hl * B_HALF + r * BST + cn;                \
            cpa16((unsigned)__cvta_generic_to_shared(dp), sp, ok ? 16 : 0);        \
        }                                                                          \
        asm volatile("cp.async.commit_group;\n");                                  \
    };                                                                             \
    load_stage(0);                                                                 \
    for (int it = 0; it < T; it++) {                                               \
        if (it + 1 < T) {                                                          \
            load_stage(it + 1);                                                    \
            asm volatile("cp.async.wait_group 1;\n");                              \
        } else {                                                                   \
            asm volatile("cp.async.wait_group 0;\n");                              \
        }                                                                          \
        __syncthreads();                                                           \
        const int ksEnd = (K - it * 32 >= 32) ? 32 : 16;                           \
        const bf16* S = smem + (it & 1) * STAGE_ELEMS;                             \
        const bf16* sAh = S;                                                       \
        const bf16* sAl = S + A_HALF;                                              \
        const bf16* sBh = S + 2 * A_HALF;                                          \
        const bf16* sBl = S + 2 * A_HALF + B_HALF;                                 \
        _Pragma("unroll") for (int ks = 0; ks < 32; ks += 16) {                    \
            if (ks >= ksEnd) break;                                                \
            unsigned aFh[2][4], aFl[2][4];                                         \
            _Pragma("unroll") for (int mt = 0; mt < 2; mt++) {                     \
                int row = wm * 32 + mt * 16 + (lane & 7) + ((lane >> 3) & 1) * 8;  \
                int col = ks + (lane >> 4) * 8;                                    \
                ldsm_x4(aFh[mt], (unsigned)__cvta_generic_to_shared(sAh + row * AST + col)); \
                ldsm_x4(aFl[mt], (unsigned)__cvta_generic_to_shared(sAl + row * AST + col)); \
            }                                                                      \
            _Pragma("unroll") for (int nt = 0; nt < 8; nt++) {                     \
                int brow = ks + (lane & 15);                                       \
                int bcol = wn * 64 + nt * 8;                                       \
                unsigned bFh[2], bFl[2];                                           \
                ldsm_x2t(bFh, (unsigned)__cvta_generic_to_shared(sBh + brow * BST + bcol)); \
                ldsm_x2t(bFl, (unsigned)__cvta_generic_to_shared(sBl + brow * BST + bcol)); \
                _Pragma("unroll") for (int mt = 0; mt < 2; mt++) {                 \
                    mma16816(acc[mt][nt], aFh[mt], bFh);                           \
                    mma16816(acc[mt][nt], aFl[mt], bFh);                           \
                    mma16816(acc[mt][nt], aFh[mt], bFl);                           \
                }                                                                  \
            }                                                                      \
        }                                                                          \
        __syncthreads();                                                           \
    }

// ---------------- GEMM with C output (node projections) ----------------
__global__ __launch_bounds__(256, 2) void k_gemm_bf3(const bf16* __restrict__ Ah,
                                                     const bf16* __restrict__ Al,
                                                     const bf16* __restrict__ Bh,
                                                     const bf16* __restrict__ Bl,
                                                     const float* __restrict__ biasA,
                                                     const float* __restrict__ biasB,
                                                     int nsplit,
                                                     float* __restrict__ C,
                                                     int M, int K, int Ncol)
{
    extern __shared__ bf16 smem[];
    const int tid = threadIdx.x;
    const int lane = tid & 31, w = tid >> 5;
    const int wm = w & 3, wn = w >> 2;
    const int m0 = blockIdx.y * 128, n0 = blockIdx.x * 128;

    GEMM_MAINLOOP(Ah, Al, Bh, Bl, M, K, Ncol)

    auto bget = [&](int c) -> float {
        if (!biasA) return 0.f;
        return (c < nsplit) ? __ldg(biasA + c) : __ldg(biasB + c - nsplit);
    };

#pragma unroll
    for (int mt = 0; mt < 2; mt++) {
#pragma unroll
        for (int nt = 0; nt < 8; nt++) {
            int r = m0 + wm * 32 + mt * 16 + (lane >> 2);
            int c = n0 + wn * 64 + nt * 8 + (lane & 3) * 2;
            float b0 = bget(c), b1 = bget(c + 1);
            if (r < M)
                *(float2*)(C + (size_t)r * Ncol + c) =
                    make_float2(acc[mt][nt][0] + b0, acc[mt][nt][1] + b1);
            if (r + 8 < M)
                *(float2*)(C + (size_t)(r + 8) * Ncol + c) =
                    make_float2(acc[mt][nt][2] + b0, acc[mt][nt][3] + b1);
        }
    }
}

// ---------------- ef GEMM (bf16x3) with fused logit epilogue ----------------
__global__ __launch_bounds__(256, 2) void k_gemm_logit(const bf16* __restrict__ Ah,
                                                       const bf16* __restrict__ Al,
                                                       const bf16* __restrict__ Bh,
                                                       const bf16* __restrict__ Bl,
                                                       const float* __restrict__ att,
                                                       const float* __restrict__ xlr,
                                                       int rstride, int half,
                                                       float* __restrict__ logitOut,
                                                       int headShift,
                                                       int M, int K, int Ncol)
{
    extern __shared__ bf16 smem[];
    const int tid = threadIdx.x;
    const int lane = tid & 31, w = tid >> 5;
    const int wm = w & 3, wn = w >> 2;
    const int m0 = blockIdx.y * 128, n0 = blockIdx.x * 128;

    GEMM_MAINLOOP(Ah, Al, Bh, Bl, M, K, Ncol)

    const int head = (n0 + wn * 64) >> headShift;
    float pl[2][2];
#pragma unroll
    for (int mt = 0; mt < 2; mt++) {
#pragma unroll
        for (int rh = 0; rh < 2; rh++) {
            pl[mt][rh] = 0.f;
            int r = m0 + wm * 32 + mt * 16 + (lane >> 2) + rh * 8;
            if (r >= M) continue;
            int s = g_src[r], dd = g_dst[r];
            const float* xlrow = xlr + (size_t)s * rstride;
            const float* xrrow = xlr + (size_t)dd * rstride + half;
            float sum = 0.f;
#pragma unroll
            for (int nt = 0; nt < 8; nt++) {
                int c = n0 + wn * 64 + nt * 8 + (lane & 3) * 2;
                float2 xlv = *(const float2*)(xlrow + c);
                float2 xrv = *(const float2*)(xrrow + c);
                float a0 = __ldg(att + c), a1 = __ldg(att + c + 1);
                float v0 = acc[mt][nt][rh * 2 + 0] + xlv.x + xrv.x;
                float v1 = acc[mt][nt][rh * 2 + 1] + xlv.y + xrv.y;
                v0 = v0 > 0.f ? v0 : 0.2f * v0;
                v1 = v1 > 0.f ? v1 : 0.2f * v1;
                sum += a0 * v0 + a1 * v1;
            }
            pl[mt][rh] = sum;
        }
    }
#pragma unroll
    for (int mt = 0; mt < 2; mt++)
#pragma unroll
        for (int rh = 0; rh < 2; rh++) {
            pl[mt][rh] += __shfl_xor_sync(0xffffffffu, pl[mt][rh], 1);
            pl[mt][rh] += __shfl_xor_sync(0xffffffffu, pl[mt][rh], 2);
        }
    if ((lane & 3) == 0) {
#pragma unroll
        for (int mt = 0; mt < 2; mt++)
#pragma unroll
            for (int rh = 0; rh < 2; rh++) {
                int r = m0 + wm * 32 + mt * 16 + (lane >> 2) + rh * 8;
                if (r < M) atomicAdd(logitOut + (size_t)r * 4 + head, pl[mt][rh]);
            }
    }
}

// ---------------- fused GATv2 layer 1 (sync-free) ----------------
__global__ __launch_bounds__(256) void k_gat1(const float* __restrict__ bias)
{
    const int node = blockIdx.x;
    const int t = threadIdx.x;
    const int c0 = t * 4;
    const int h = t >> 6;

    float m = -1e30f, d = 0.f;
    float4 acc = make_float4(0.f, 0.f, 0.f, 0.f);
    const int beg = g_offs[node], end = g_offs[node + 1];

    for (int k = beg; k < end; k++) {
        const int e = g_perm[k];
        const int s = g_src[e];
        float lg = __ldg(g_logit1 + (size_t)e * 4 + h);
        float4 xl = *(const float4*)(g_xlr1 + (size_t)s * 2048 + c0);
        float mn = fmaxf(m, lg);
        float sc = __expf(m - mn), wv = __expf(lg - mn);
        d = d * sc + wv;
        acc.x = acc.x * sc + wv * xl.x;
        acc.y = acc.y * sc + wv * xl.y;
        acc.z = acc.z * sc + wv * xl.z;
        acc.w = acc.w * sc + wv * xl.w;
        m = mn;
    }

    float inv = 1.f / (d + 1e-16f);
    float4 bv = *(const float4*)(bias + c0);
    float o0 = fmaxf(acc.x * inv + bv.x, 0.f);
    float o1 = fmaxf(acc.y * inv + bv.y, 0.f);
    float o2 = fmaxf(acc.z * inv + bv.z, 0.f);
    float o3 = fmaxf(acc.w * inv + bv.w, 0.f);
    bf16 h0 = __float2bfloat16_rn(o0), h1v = __float2bfloat16_rn(o1);
    bf16 h2 = __float2bfloat16_rn(o2), h3 = __float2bfloat16_rn(o3);
    bf16* ph = g_h1h + (size_t)node * D1 + c0;
    bf16* pl = g_h1l + (size_t)node * D1 + c0;
    ph[0] = h0; ph[1] = h1v; ph[2] = h2; ph[3] = h3;
    pl[0] = __float2bfloat16_rn(o0 - __bfloat162float(h0));
    pl[1] = __float2bfloat16_rn(o1 - __bfloat162float(h1v));
    pl[2] = __float2bfloat16_rn(o2 - __bfloat162float(h2));
    pl[3] = __float2bfloat16_rn(o3 - __bfloat162float(h3));
}

// ---------------- fused GATv2 layer 2 (sync-free) ----------------
__global__ __launch_bounds__(256) void k_gat2(const float* __restrict__ bias)
{
    const int node = blockIdx.x;
    const int t = threadIdx.x;
    const int h = t >> 6;

    float m = -1e30f, d = 0.f, acc = 0.f;
    const int beg = g_offs[node], end = g_offs[node + 1];

    for (int k = beg; k < end; k++) {
        const int e = g_perm[k];
        const int s = g_src[e];
        float lg = __ldg(g_logit2 + (size_t)e * 4 + h);
        float xl = g_xlr2[(size_t)s * 512 + t];
        float mn = fmaxf(m, lg);
        float sc = __expf(m - mn), wv = __expf(lg - mn);
        d = d * sc + wv;
        acc = acc * sc + wv * xl;
        m = mn;
    }

    float o = acc / (d + 1e-16f);
    g_h2[(size_t)node * D2 + t] = fmaxf(o + bias[t], 0.f);
}

// ---------------- MLP head ----------------
__global__ void k_mlp(const void* __restrict__ n_nodes,
                      const float* __restrict__ fc1w, const float* __restrict__ fc1b,
                      const float* __restrict__ fc2w, const float* __restrict__ fc2b,
                      float* __restrict__ out)
{
    const int b = blockIdx.x;
    const int t = threadIdx.x;  // 64
    __shared__ float master[D2];
    __shared__ int s_last;
    __shared__ float ws[2];

    if (t == 0) {
        const int* w = (const int*)n_nodes;
        bool is64 = (w[1] == 0);
        long long cum = 0;
        if (is64) {
            const long long* l = (const long long*)n_nodes;
            for (int i = 0; i <= b; i++) cum += l[i];
        } else {
            for (int i = 0; i <= b; i++) cum += w[i];
        }
        s_last = (int)cum - 1;
    }
    __syncthreads();
    const int node = s_last;
    for (int i = t; i < D2; i += 64) master[i] = g_h2[(size_t)node * D2 + i];
    __syncthreads();

    float z = fc1b[t];
    for (int c = 0; c < D2; c++) z += master[c] * fc1w[c * 64 + t];
    z = fmaxf(z, 0.f);
    float v = z * fc2w[t];
#pragma unroll
    for (int off = 16; off; off >>= 1) v += __shfl_xor_sync(0xffffffffu, v, off);
    if ((t & 31) == 0) ws[t >> 5] = v;
    __syncthreads();
    if (t == 0) out[b] = ws[0] + ws[1] + fc2b[0];
}

// ---------------- launch ----------------
extern "C" void kernel_launch(void* const* d_in, const int* in_sizes, int n_in,
                              void* d_out, int out_size)
{
    const float* x    = (const float*)d_in[0];
    const void*  ei   = d_in[1];
    const float* ea   = (const float*)d_in[2];
    const void*  nnod = d_in[3];
    const float* Wl1  = (const float*)d_in[4];
    const float* bl1  = (const float*)d_in[5];
    const float* Wr1  = (const float*)d_in[6];
    const float* br1  = (const float*)d_in[7];
    const float* We1  = (const float*)d_in[8];
    const float* att1 = (const float*)d_in[9];
    const float* b1   = (const float*)d_in[10];
    const float* Wl2  = (const float*)d_in[11];
    const float* bl2  = (const float*)d_in[12];
    const float* Wr2  = (const float*)d_in[13];
    const float* br2  = (const float*)d_in[14];
    const float* We2  = (const float*)d_in[15];
    const float* att2 = (const float*)d_in[16];
    const float* b2   = (const float*)d_in[17];
    const float* fc1w = (const float*)d_in[18];
    const float* fc1b = (const float*)d_in[19];
    const float* fc2w = (const float*)d_in[20];
    const float* fc2b = (const float*)d_in[21];
    float* out = (float*)d_out;

    float *xlr1, *xlr2, *lg1, *lg2;
    bf16 *xh, *xlo, *eah, *eal, *h1h, *h1l, *w1h, *w1l, *w2h, *w2l;
    bf16 *we1h, *we1l, *we2h, *we2l;
    cudaGetSymbolAddress((void**)&xlr1, g_xlr1);
    cudaGetSymbolAddress((void**)&xlr2, g_xlr2);
    cudaGetSymbolAddress((void**)&lg1, g_logit1);
    cudaGetSymbolAddress((void**)&lg2, g_logit2);
    cudaGetSymbolAddress((void**)&xh,  g_xh);
    cudaGetSymbolAddress((void**)&xlo, g_xlo);
    cudaGetSymbolAddress((void**)&eah, g_eah);
    cudaGetSymbolAddress((void**)&eal, g_eal);
    cudaGetSymbolAddress((void**)&h1h, g_h1h);
    cudaGetSymbolAddress((void**)&h1l, g_h1l);
    cudaGetSymbolAddress((void**)&w1h, g_w1h); cudaGetSymbolAddress((void**)&w1l, g_w1l);
    cudaGetSymbolAddress((void**)&w2h, g_w2h); cudaGetSymbolAddress((void**)&w2l, g_w2l);
    cudaGetSymbolAddress((void**)&we1h, g_we1h); cudaGetSymbolAddress((void**)&we1l, g_we1l);
    cudaGetSymbolAddress((void**)&we2h, g_we2h); cudaGetSymbolAddress((void**)&we2l, g_we2l);

    cudaFuncSetAttribute(k_gemm_bf3,
                         cudaFuncAttributeMaxDynamicSharedMemorySize, SMEM_BYTES);
    cudaFuncSetAttribute(k_gemm_logit,
                         cudaFuncAttributeMaxDynamicSharedMemorySize, SMEM_BYTES);

    const int TB = 256;

    cudaEventRecord(g_evF, 0);

    // ---- s2: CSR build + layer-2 weight splits ----
    cudaStreamWaitEvent(g_s2, g_evF, 0);
    k_zero<<<(NN + TB - 1) / TB, TB, 0, g_s2>>>();
    k_convert<<<(EE + TB - 1) / TB, TB, 0, g_s2>>>(ei);
    cudaEventRecord(g_evConv, g_s2);
    k_count<<<(EE + TB - 1) / TB, TB, 0, g_s2>>>();
    k_scanA<<<NB, 256, 0, g_s2>>>();
    k_scanB<<<1, 256, 0, g_s2>>>();
    k_scanC<<<NB, 256, 0, g_s2>>>();
    k_scatter<<<(EE + TB - 1) / TB, TB, 0, g_s2>>>();
    k_split2<<<(1024 * 256 + 255) / 256, 256, 0, g_s2>>>(Wl2, w2h, w2l, 1024, 256, 512, 0);
    k_split2<<<(1024 * 256 + 255) / 256, 256, 0, g_s2>>>(Wr2, w2h, w2l, 1024, 256, 512, 256);
    cudaEventRecord(g_evJ1, g_s2);

    // ---- s1: logit zero + edge/We splits ----
    cudaStreamWaitEvent(g_s1, g_evF, 0);
    k_zerof<<<(EE * 4 + 255) / 256, 256, 0, g_s1>>>(lg1, EE * 4);
    k_zerof<<<(EE * 4 + 255) / 256, 256, 0, g_s1>>>(lg2, EE * 4);
    k_split<<<(EE * 16 + 255) / 256, 256, 0, g_s1>>>(ea, eah, eal, EE * 16);
    k_split<<<(16 * 1024 + 255) / 256, 256, 0, g_s1>>>(We1, we1h, we1l, 16 * 1024);
    k_split<<<(16 * 256 + 255) / 256, 256, 0, g_s1>>>(We2, we2h, we2l, 16 * 256);
    cudaEventRecord(g_evS1, g_s1);

    // ---- main: node splits + layer-1 GEMM ----
    k_split<<<(NN * 128 + 255) / 256, 256>>>(x, xh, xlo, NN * 128);
    k_split2<<<(128 * 1024 + 255) / 256, 256>>>(Wl1, w1h, w1l, 128, 1024, 2048, 0);
    k_split2<<<(128 * 1024 + 255) / 256, 256>>>(Wr1, w1h, w1l, 128, 1024, 2048, 1024);
    {
        dim3 g1(2048 / 128, NN / 128);
        k_gemm_bf3<<<g1, 256, SMEM_BYTES>>>(xh, xlo, w1h, w1l, bl1, br1, 1024,
                                            xlr1, NN, 128, 2048);
    }

    // ---- main: edge-logit GEMM layer 1 ----
    cudaStreamWaitEvent(0, g_evConv, 0);
    cudaStreamWaitEvent(0, g_evS1, 0);
    {
        dim3 ge(1024 / 128, (EE + 127) / 128);
        k_gemm_logit<<<ge, 256, SMEM_BYTES>>>(eah, eal, we1h, we1l, att1,
                                              xlr1, 2048, 1024, lg1, 8,
                                              EE, 16, 1024);
    }

    // ---- main: gat1, layer-2 GEMM, logit 2, gat2, mlp ----
    cudaStreamWaitEvent(0, g_evJ1, 0);
    k_gat1<<<NN, 256>>>(b1);
    {
        dim3 g2(512 / 128, NN / 128);
        k_gemm_bf3<<<g2, 256, SMEM_BYTES>>>(h1h, h1l, w2h, w2l, bl2, br2, 256,
                                            xlr2, NN, 1024, 512);
    }
    {
        dim3 ge(256 / 128, (EE + 127) / 128);
        k_gemm_logit<<<ge, 256, SMEM_BYTES>>>(eah, eal, we2h, we2l, att2,
                                              xlr2, 512, 256, lg2, 6,
                                              EE, 16, 256);
    }
    k_gat2<<<NN, 256>>>(b2);

    k_mlp<<<BB, 64>>>(nnod, fc1w, fc1b, fc2w, fc2b, out);
}